// round 1
// baseline (speedup 1.0000x reference)
#include <cuda_runtime.h>
#include <math_constants.h>
#include <cstdint>

#define RR 32
#define R3 32768
#define C 240
#define C2 480
#define NB 4
#define NP 32768
#define BN_EPS 1e-5f

// ---------------- static scratch (no allocations allowed) ----------------
__device__ float g_mean[NB][3];
__device__ float g_scale[NB];
__device__ int   g_pos[NB * NP];
__device__ int   g_count[NB * R3];
__device__ int   g_offset[NB * R3];
__device__ int   g_cursor[NB * R3];
__device__ int   g_plist[NB * NP];
__device__ float g_ft[(size_t)NB * NP * C];     // features transposed [B][N][C]
__device__ float g_fea[(size_t)NB * R3 * C2];   // voxel features [B][V][2C] (max;min)
__device__ float g_bnA[C];
__device__ float g_bnB[C];

// ---------------- K1: per-batch coord mean + scale ----------------
__global__ void k_coordstats(const float* __restrict__ coords) {
    int b = blockIdx.x;
    const float* cx = coords + (size_t)b * 3 * NP;
    const float* cy = cx + NP;
    const float* cz = cy + NP;
    float sx = 0.f, sy = 0.f, sz = 0.f;
    for (int n = threadIdx.x; n < NP; n += blockDim.x) {
        sx += cx[n]; sy += cy[n]; sz += cz[n];
    }
    __shared__ float sh[3][32];
    __shared__ float mean[3];
    int lane = threadIdx.x & 31, warp = threadIdx.x >> 5;
    #pragma unroll
    for (int o = 16; o; o >>= 1) {
        sx += __shfl_down_sync(0xffffffffu, sx, o);
        sy += __shfl_down_sync(0xffffffffu, sy, o);
        sz += __shfl_down_sync(0xffffffffu, sz, o);
    }
    if (lane == 0) { sh[0][warp] = sx; sh[1][warp] = sy; sh[2][warp] = sz; }
    __syncthreads();
    if (threadIdx.x == 0) {
        int nw = blockDim.x >> 5;
        float tx = 0.f, ty = 0.f, tz = 0.f;
        for (int i = 0; i < nw; i++) { tx += sh[0][i]; ty += sh[1][i]; tz += sh[2][i]; }
        mean[0] = tx / (float)NP; mean[1] = ty / (float)NP; mean[2] = tz / (float)NP;
    }
    __syncthreads();
    float m0 = mean[0], m1 = mean[1], m2 = mean[2];
    float mx = 0.f;
    for (int n = threadIdx.x; n < NP; n += blockDim.x) {
        float dx = cx[n] - m0, dy = cy[n] - m1, dz = cz[n] - m2;
        mx = fmaxf(mx, sqrtf(dx * dx + dy * dy + dz * dz));
    }
    #pragma unroll
    for (int o = 16; o; o >>= 1) mx = fmaxf(mx, __shfl_down_sync(0xffffffffu, mx, o));
    if (lane == 0) sh[0][warp] = mx;
    __syncthreads();
    if (threadIdx.x == 0) {
        int nw = blockDim.x >> 5;
        float t = 0.f;
        for (int i = 0; i < nw; i++) t = fmaxf(t, sh[0][i]);
        g_scale[b] = t * 2.0f;   // EPS_NORM = 0
        g_mean[b][0] = m0; g_mean[b][1] = m1; g_mean[b][2] = m2;
    }
}

// ---------------- K0: zero voxel counts (graph replays reuse state) ----------------
__global__ void k_zero_counts() {
    int i = blockIdx.x * blockDim.x + threadIdx.x;
    if (i < NB * R3) g_count[i] = 0;
}

// ---------------- K2: nc + voxel id + count ----------------
__global__ void k_voxelize(const float* __restrict__ coords, float* __restrict__ nc_out,
                           int write_nc) {
    int i = blockIdx.x * blockDim.x + threadIdx.x;
    if (i >= NB * NP) return;
    int b = i >> 15, n = i & (NP - 1);
    const float* base = coords + (size_t)b * 3 * NP;
    float sc = g_scale[b];
    int vx[3];
    #pragma unroll
    for (int ch = 0; ch < 3; ch++) {
        float x = base[ch * NP + n];
        float u = (x - g_mean[b][ch]) / sc + 0.5f;
        float t = fminf(fmaxf(u * (float)RR, 0.0f), (float)(RR - 1));
        if (write_nc) nc_out[((size_t)b * 3 + ch) * NP + n] = t;
        vx[ch] = (int)rintf(t);   // round half to even, like jnp.round
    }
    int pos = vx[0] + vx[1] * RR + vx[2] * RR * RR;
    g_pos[i] = pos;
    atomicAdd(&g_count[(b << 15) + pos], 1);
}

// ---------------- K3: per-batch exclusive scan of counts ----------------
__global__ void k_scan() {
    int b = blockIdx.x;
    int t = threadIdx.x;                // 1024 threads, 32 counts each
    int base = b * R3 + t * 32;
    int local[32];
    int s = 0;
    #pragma unroll
    for (int i = 0; i < 32; i++) { local[i] = s; s += g_count[base + i]; }
    __shared__ int warp_sums[32];
    int lane = t & 31, warp = t >> 5;
    int v = s;
    #pragma unroll
    for (int o = 1; o < 32; o <<= 1) {
        int u = __shfl_up_sync(0xffffffffu, v, o);
        if (lane >= o) v += u;
    }
    if (lane == 31) warp_sums[warp] = v;
    __syncthreads();
    if (warp == 0) {
        int w = warp_sums[lane];
        #pragma unroll
        for (int o = 1; o < 32; o <<= 1) {
            int u = __shfl_up_sync(0xffffffffu, w, o);
            if (lane >= o) w += u;
        }
        warp_sums[lane] = w;   // inclusive
    }
    __syncthreads();
    int excl = v - s + (warp ? warp_sums[warp - 1] : 0);
    #pragma unroll
    for (int i = 0; i < 32; i++) {
        int off = excl + local[i];
        g_offset[base + i] = off;
        g_cursor[base + i] = off;
    }
}

// ---------------- K4: scatter point indices into per-voxel lists ----------------
__global__ void k_scatter() {
    int i = blockIdx.x * blockDim.x + threadIdx.x;
    if (i >= NB * NP) return;
    int b = i >> 15, n = i & (NP - 1);
    int pos = g_pos[i];
    int slot = atomicAdd(&g_cursor[(b << 15) + pos], 1);
    g_plist[(b << 15) + slot] = n;
}

// ---------------- K5: transpose features [B,C,N] -> [B,N,C] ----------------
__global__ void k_transpose(const float* __restrict__ f) {
    __shared__ float tile[32][33];
    int b = blockIdx.z;
    int n0 = blockIdx.x * 32, c0 = blockIdx.y * 32;
    int n = n0 + threadIdx.x;
    for (int j = threadIdx.y; j < 32; j += 8) {
        int c = c0 + j;
        tile[j][threadIdx.x] = (c < C) ? f[((size_t)b * C + c) * NP + n] : 0.f;
    }
    __syncthreads();
    int c = c0 + threadIdx.x;
    if (c < C) {
        for (int j = threadIdx.y; j < 32; j += 8) {
            g_ft[((size_t)b * NP + n0 + j) * C + c] = tile[threadIdx.x][j];
        }
    }
}

// ---------------- K6: per-voxel max/min gather (one warp per voxel) ----------------
__global__ void k_gather() {
    int gw = (int)((blockIdx.x * (size_t)blockDim.x + threadIdx.x) >> 5);
    if (gw >= NB * R3) return;
    int lane = threadIdx.x & 31;
    int b = gw >> 15, v = gw & (R3 - 1);
    int idx = (b << 15) + v;
    int cnt = g_count[idx];
    int off = g_offset[idx];
    float* out = g_fea + (size_t)idx * C2;
    float mx[8], mn[8];
    #pragma unroll
    for (int i = 0; i < 8; i++) { mx[i] = -CUDART_INF_F; mn[i] = CUDART_INF_F; }
    for (int p = 0; p < cnt; p++) {
        int n = g_plist[(b << 15) + off + p];
        const float* fp = g_ft + ((size_t)(b << 15) + n) * C;
        #pragma unroll
        for (int i = 0; i < 8; i++) {
            int c = i * 32 + lane;
            if (c < C) {
                float x = fp[c];
                mx[i] = fmaxf(mx[i], x);
                mn[i] = fminf(mn[i], x);
            }
        }
    }
    if (cnt == 0) {
        #pragma unroll
        for (int i = 0; i < 8; i++) { mx[i] = 0.f; mn[i] = 0.f; }
    }
    #pragma unroll
    for (int i = 0; i < 8; i++) {
        int c = i * 32 + lane;
        if (c < C) { out[c] = mx[i]; out[C + c] = mn[i]; }
    }
}

// ---------------- K7: SGEMM y[b,c,v] = sum_o w[c,o]*fea[b,v,o] + bias[c] ----------------
#define BM 128
#define BNt 128
#define BK 8
__global__ __launch_bounds__(256) void k_gemm(const float* __restrict__ w,
                                              const float* __restrict__ bias,
                                              float* __restrict__ y) {
    __shared__ float As[BK][BM];
    __shared__ float Bs[BK][BNt];
    int b = blockIdx.z;
    int c0 = blockIdx.y * BM;
    int v0 = blockIdx.x * BNt;
    int t = threadIdx.x;
    int loadRow = t >> 1;
    int loadCol = (t & 1) * 4;
    int tx = t & 15, ty = t >> 4;
    const float* fb = g_fea + ((size_t)b << 15) * C2;
    float acc[8][8];
    #pragma unroll
    for (int i = 0; i < 8; i++)
        #pragma unroll
        for (int j = 0; j < 8; j++) acc[i][j] = 0.f;

    for (int k0 = 0; k0 < C2; k0 += BK) {
        float4 av = make_float4(0.f, 0.f, 0.f, 0.f);
        int ar = c0 + loadRow;
        if (ar < C) av = *(const float4*)(w + (size_t)ar * C2 + k0 + loadCol);
        As[loadCol + 0][loadRow] = av.x;
        As[loadCol + 1][loadRow] = av.y;
        As[loadCol + 2][loadRow] = av.z;
        As[loadCol + 3][loadRow] = av.w;
        float4 bv = *(const float4*)(fb + (size_t)(v0 + loadRow) * C2 + k0 + loadCol);
        Bs[loadCol + 0][loadRow] = bv.x;
        Bs[loadCol + 1][loadRow] = bv.y;
        Bs[loadCol + 2][loadRow] = bv.z;
        Bs[loadCol + 3][loadRow] = bv.w;
        __syncthreads();
        #pragma unroll
        for (int kk = 0; kk < BK; kk++) {
            float a[8], bb[8];
            *(float4*)(a)     = *(float4*)&As[kk][ty * 8];
            *(float4*)(a + 4) = *(float4*)&As[kk][ty * 8 + 4];
            *(float4*)(bb)     = *(float4*)&Bs[kk][tx * 8];
            *(float4*)(bb + 4) = *(float4*)&Bs[kk][tx * 8 + 4];
            #pragma unroll
            for (int i = 0; i < 8; i++)
                #pragma unroll
                for (int j = 0; j < 8; j++) acc[i][j] += a[i] * bb[j];
        }
        __syncthreads();
    }
    #pragma unroll
    for (int i = 0; i < 8; i++) {
        int c = c0 + ty * 8 + i;
        if (c < C) {
            float bi = bias[c];
            float* yr = y + (((size_t)b * C + c) << 15) + v0 + tx * 8;
            float4 r0 = make_float4(acc[i][0] + bi, acc[i][1] + bi, acc[i][2] + bi, acc[i][3] + bi);
            float4 r1 = make_float4(acc[i][4] + bi, acc[i][5] + bi, acc[i][6] + bi, acc[i][7] + bi);
            *(float4*)yr = r0;
            *(float4*)(yr + 4) = r1;
        }
    }
}

// ---------------- K8: BN batch stats per channel ----------------
__global__ void k_bnstats(const float* __restrict__ y, const float* __restrict__ gamma,
                          const float* __restrict__ beta) {
    int c = blockIdx.x;
    float s = 0.f, s2 = 0.f;
    const int TOT = NB * R3;
    for (int i = threadIdx.x; i < TOT; i += blockDim.x) {
        int b = i >> 15, v = i & (R3 - 1);
        float x = y[(((size_t)b * C + c) << 15) + v];
        s += x; s2 += x * x;
    }
    __shared__ float shs[32], shs2[32];
    int lane = threadIdx.x & 31, warp = threadIdx.x >> 5;
    #pragma unroll
    for (int o = 16; o; o >>= 1) {
        s  += __shfl_down_sync(0xffffffffu, s, o);
        s2 += __shfl_down_sync(0xffffffffu, s2, o);
    }
    if (lane == 0) { shs[warp] = s; shs2[warp] = s2; }
    __syncthreads();
    if (threadIdx.x == 0) {
        int nw = blockDim.x >> 5;
        float ts = 0.f, ts2 = 0.f;
        for (int i = 0; i < nw; i++) { ts += shs[i]; ts2 += shs2[i]; }
        float mean = ts / (float)TOT;
        float var = ts2 / (float)TOT - mean * mean;
        float rstd = rsqrtf(var + BN_EPS);
        float A = gamma[c] * rstd;
        g_bnA[c] = A;
        g_bnB[c] = beta[c] - mean * A;
    }
}

// ---------------- K9: fused BN + swish, in place ----------------
__global__ void k_bnswish(float* __restrict__ y) {
    size_t i4 = (size_t)blockIdx.x * blockDim.x + threadIdx.x;
    const size_t TOT4 = (size_t)NB * C * R3 / 4;
    if (i4 >= TOT4) return;
    size_t idx = i4 * 4;
    int c = (int)((idx >> 15) % C);   // R3 = 2^15, multiple of 4 so c constant in float4
    float A = g_bnA[c], Bv = g_bnB[c];
    float4 v = *(float4*)(y + idx);
    float x0 = v.x * A + Bv, x1 = v.y * A + Bv, x2 = v.z * A + Bv, x3 = v.w * A + Bv;
    v.x = x0 / (1.f + expf(-x0));
    v.y = x1 / (1.f + expf(-x1));
    v.z = x2 / (1.f + expf(-x2));
    v.w = x3 / (1.f + expf(-x3));
    *(float4*)(y + idx) = v;
}

// ---------------- launch ----------------
extern "C" void kernel_launch(void* const* d_in, const int* in_sizes, int n_in,
                              void* d_out, int out_size) {
    const float* features = (const float*)d_in[0];
    const float* coords   = (const float*)d_in[1];
    const float* w        = (const float*)d_in[2];
    const float* bias     = (const float*)d_in[3];
    const float* gamma    = (const float*)d_in[4];
    const float* beta     = (const float*)d_in[5];
    float* out = (float*)d_out;

    const int Y_SIZE = NB * C * R3;           // 31457280
    const int NC_SIZE = NB * 3 * NP;          // 393216
    int write_nc = (out_size >= Y_SIZE + NC_SIZE) ? 1 : 0;
    float* nc_out = out + Y_SIZE;

    k_coordstats<<<NB, 1024>>>(coords);
    k_zero_counts<<<(NB * R3 + 255) / 256, 256>>>();
    k_voxelize<<<(NB * NP + 255) / 256, 256>>>(coords, nc_out, write_nc);
    k_scan<<<NB, 1024>>>();
    k_scatter<<<(NB * NP + 255) / 256, 256>>>();
    {
        dim3 blk(32, 8);
        dim3 grd(NP / 32, (C + 31) / 32, NB);
        k_transpose<<<grd, blk>>>(features);
    }
    k_gather<<<(NB * R3) / 8, 256>>>();
    {
        dim3 grd(R3 / BNt, (C + BM - 1) / BM, NB);
        k_gemm<<<grd, 256>>>(w, bias, out);
    }
    k_bnstats<<<C, 256>>>(out, gamma, beta);
    {
        size_t tot4 = (size_t)NB * C * R3 / 4;
        k_bnswish<<<(unsigned)((tot4 + 255) / 256), 256>>>(out);
    }
}

// round 6
// speedup vs baseline: 2.1216x; 2.1216x over previous
#include <cuda_runtime.h>
#include <math_constants.h>
#include <cstdint>

#define RR 32
#define R3 32768
#define C 240
#define C2 480
#define NB 4
#define NP 32768
#define NVOX (NB * R3)
#define BN_EPS 1e-5f

// ---------------- static scratch ----------------
__device__ float g_mean[NB][3];
__device__ float g_scale[NB];
__device__ int   g_pos[NB * NP];
__device__ int   g_count[NVOX];
__device__ int   g_offset[NVOX];
__device__ int   g_plist[NB * NP];
__device__ float g_ft[(size_t)NB * NP * C];     // features transposed [B][N][C]
__device__ float g_fea[(size_t)NVOX * C2];      // voxel features [V][2C] (tf32-rounded)
__device__ float g_wr[256 * C2];                // weights padded to 256 rows, tf32-rounded
__device__ float g_bnA[C];
__device__ float g_bnB[C];

// ---------------- helpers ----------------
__device__ __forceinline__ float tf32_rna(float x) {
    uint32_t u; asm("cvt.rna.tf32.f32 %0, %1;" : "=r"(u) : "f"(x));
    return __uint_as_float(u);
}
__device__ __forceinline__ uint32_t smem_u32(const void* p) {
    uint32_t a;
    asm("{ .reg .u64 t; cvta.to.shared.u64 t, %1; cvt.u32.u64 %0, t; }" : "=r"(a) : "l"(p));
    return a;
}
__device__ __forceinline__ void cp_async16(uint32_t dst, const void* src) {
    asm volatile("cp.async.cg.shared.global [%0], [%1], 16;" :: "r"(dst), "l"(src) : "memory");
}
__device__ __forceinline__ void ldsm_x4(uint32_t* r, uint32_t addr) {
    asm volatile("ldmatrix.sync.aligned.m8n8.x4.shared.b16 {%0,%1,%2,%3}, [%4];"
                 : "=r"(r[0]), "=r"(r[1]), "=r"(r[2]), "=r"(r[3]) : "r"(addr));
}
__device__ __forceinline__ void mma_tf32(float* c, const uint32_t* a, uint32_t b0, uint32_t b1) {
    asm volatile("mma.sync.aligned.m16n8k8.row.col.f32.tf32.tf32.f32 "
                 "{%0,%1,%2,%3}, {%4,%5,%6,%7}, {%8,%9}, {%0,%1,%2,%3};"
                 : "+f"(c[0]), "+f"(c[1]), "+f"(c[2]), "+f"(c[3])
                 : "r"(a[0]), "r"(a[1]), "r"(a[2]), "r"(a[3]), "r"(b0), "r"(b1));
}

// ---------------- K1: per-batch coord mean + scale ----------------
__global__ void k_coordstats(const float* __restrict__ coords) {
    int b = blockIdx.x;
    const float4* cx = (const float4*)(coords + (size_t)b * 3 * NP);
    const float4* cy = cx + NP / 4;
    const float4* cz = cy + NP / 4;
    float sx = 0.f, sy = 0.f, sz = 0.f;
    for (int n = threadIdx.x; n < NP / 4; n += blockDim.x) {
        float4 a = cx[n], c = cy[n], d = cz[n];
        sx += (a.x + a.y) + (a.z + a.w);
        sy += (c.x + c.y) + (c.z + c.w);
        sz += (d.x + d.y) + (d.z + d.w);
    }
    __shared__ float sh[3][32];
    __shared__ float mean[3];
    int lane = threadIdx.x & 31, warp = threadIdx.x >> 5;
    #pragma unroll
    for (int o = 16; o; o >>= 1) {
        sx += __shfl_down_sync(0xffffffffu, sx, o);
        sy += __shfl_down_sync(0xffffffffu, sy, o);
        sz += __shfl_down_sync(0xffffffffu, sz, o);
    }
    if (lane == 0) { sh[0][warp] = sx; sh[1][warp] = sy; sh[2][warp] = sz; }
    __syncthreads();
    if (threadIdx.x == 0) {
        int nw = blockDim.x >> 5;
        float tx = 0.f, ty = 0.f, tz = 0.f;
        for (int i = 0; i < nw; i++) { tx += sh[0][i]; ty += sh[1][i]; tz += sh[2][i]; }
        mean[0] = tx / (float)NP; mean[1] = ty / (float)NP; mean[2] = tz / (float)NP;
    }
    __syncthreads();
    float m0 = mean[0], m1 = mean[1], m2 = mean[2];
    float mx = 0.f;
    for (int n = threadIdx.x; n < NP / 4; n += blockDim.x) {
        float4 a = cx[n], c = cy[n], d = cz[n];
        float dx, dy, dz, q;
        dx = a.x - m0; dy = c.x - m1; dz = d.x - m2; q = dx*dx + dy*dy + dz*dz; mx = fmaxf(mx, q);
        dx = a.y - m0; dy = c.y - m1; dz = d.y - m2; q = dx*dx + dy*dy + dz*dz; mx = fmaxf(mx, q);
        dx = a.z - m0; dy = c.z - m1; dz = d.z - m2; q = dx*dx + dy*dy + dz*dz; mx = fmaxf(mx, q);
        dx = a.w - m0; dy = c.w - m1; dz = d.w - m2; q = dx*dx + dy*dy + dz*dz; mx = fmaxf(mx, q);
    }
    #pragma unroll
    for (int o = 16; o; o >>= 1) mx = fmaxf(mx, __shfl_down_sync(0xffffffffu, mx, o));
    if (lane == 0) sh[0][warp] = mx;
    __syncthreads();
    if (threadIdx.x == 0) {
        int nw = blockDim.x >> 5;
        float t = 0.f;
        for (int i = 0; i < nw; i++) t = fmaxf(t, sh[0][i]);
        g_scale[b] = sqrtf(t) * 2.0f;
        g_mean[b][0] = m0; g_mean[b][1] = m1; g_mean[b][2] = m2;
    }
}

// ---------------- K0: zero voxel counts ----------------
__global__ void k_zero_counts() {
    int i = blockIdx.x * blockDim.x + threadIdx.x;
    if (i < NVOX) g_count[i] = 0;
}

// ---------------- K2: nc + voxel id + count ----------------
__global__ void k_voxelize(const float* __restrict__ coords, float* __restrict__ nc_out,
                           int write_nc) {
    int i = blockIdx.x * blockDim.x + threadIdx.x;
    if (i >= NB * NP) return;
    int b = i >> 15, n = i & (NP - 1);
    const float* base = coords + (size_t)b * 3 * NP;
    float sc = g_scale[b];
    int vx[3];
    #pragma unroll
    for (int ch = 0; ch < 3; ch++) {
        float x = base[ch * NP + n];
        float u = (x - g_mean[b][ch]) / sc + 0.5f;
        float t = fminf(fmaxf(u * (float)RR, 0.0f), (float)(RR - 1));
        if (write_nc) nc_out[((size_t)b * 3 + ch) * NP + n] = t;
        vx[ch] = (int)rintf(t);
    }
    int pos = vx[0] + vx[1] * RR + vx[2] * RR * RR;
    g_pos[i] = pos;
    atomicAdd(&g_count[(b << 15) + pos], 1);
}

// ---------------- K3: per-batch exclusive scan ----------------
__global__ void k_scan() {
    int b = blockIdx.x;
    int t = threadIdx.x;
    int base = b * R3 + t * 32;
    int4 v[8];
    const int4* src = (const int4*)(g_count + base);
    #pragma unroll
    for (int j = 0; j < 8; j++) v[j] = src[j];
    int s = 0;
    #pragma unroll
    for (int j = 0; j < 8; j++) s += v[j].x + v[j].y + v[j].z + v[j].w;
    __shared__ int warp_sums[32];
    int lane = t & 31, warp = t >> 5;
    int inc = s;
    #pragma unroll
    for (int o = 1; o < 32; o <<= 1) {
        int u = __shfl_up_sync(0xffffffffu, inc, o);
        if (lane >= o) inc += u;
    }
    if (lane == 31) warp_sums[warp] = inc;
    __syncthreads();
    if (warp == 0) {
        int w = warp_sums[lane];
        #pragma unroll
        for (int o = 1; o < 32; o <<= 1) {
            int u = __shfl_up_sync(0xffffffffu, w, o);
            if (lane >= o) w += u;
        }
        warp_sums[lane] = w;
    }
    __syncthreads();
    int run = inc - s + (warp ? warp_sums[warp - 1] : 0);
    int4* dst = (int4*)(g_offset + base);
    #pragma unroll
    for (int j = 0; j < 8; j++) {
        int4 o;
        o.x = run; run += v[j].x;
        o.y = run; run += v[j].y;
        o.z = run; run += v[j].z;
        o.w = run; run += v[j].w;
        dst[j] = o;
    }
}

// ---------------- K4: scatter (bumps g_offset; end = start + cnt) ----------------
__global__ void k_scatter() {
    int i = blockIdx.x * blockDim.x + threadIdx.x;
    if (i >= NB * NP) return;
    int b = i >> 15, n = i & (NP - 1);
    int pos = g_pos[i];
    int slot = atomicAdd(&g_offset[(b << 15) + pos], 1);
    g_plist[(b << 15) + slot] = n;
}

// ---------------- K5: transpose features [B,C,N] -> [B,N,C] ----------------
__global__ void k_transpose(const float* __restrict__ f) {
    __shared__ float tile[32][33];
    int b = blockIdx.z;
    int n0 = blockIdx.x * 32, c0 = blockIdx.y * 32;
    int n = n0 + threadIdx.x;
    for (int j = threadIdx.y; j < 32; j += 8) {
        int c = c0 + j;
        tile[j][threadIdx.x] = (c < C) ? f[((size_t)b * C + c) * NP + n] : 0.f;
    }
    __syncthreads();
    int c = c0 + threadIdx.x;
    if (c < C) {
        for (int j = threadIdx.y; j < 32; j += 8) {
            g_ft[((size_t)b * NP + n0 + j) * C + c] = tile[threadIdx.x][j];
        }
    }
}

// ---------------- K6: per-voxel max/min gather, tf32-rounded output ----------------
__global__ void k_gather() {
    int gw = (int)((blockIdx.x * (size_t)blockDim.x + threadIdx.x) >> 5);
    if (gw >= NVOX) return;
    int lane = threadIdx.x & 31;
    int b = gw >> 15;
    int idx = gw;
    int cnt = g_count[idx];
    int start = g_offset[idx] - cnt;
    float* out = g_fea + (size_t)idx * C2;
    float mx[8], mn[8];
    #pragma unroll
    for (int i = 0; i < 8; i++) { mx[i] = -CUDART_INF_F; mn[i] = CUDART_INF_F; }
    for (int p = 0; p < cnt; p++) {
        int n = g_plist[(b << 15) + start + p];
        const float* fp = g_ft + ((size_t)(b << 15) + n) * C;
        #pragma unroll
        for (int i = 0; i < 8; i++) {
            int c = i * 32 + lane;
            if (c < C) {
                float x = fp[c];
                mx[i] = fmaxf(mx[i], x);
                mn[i] = fminf(mn[i], x);
            }
        }
    }
    if (cnt == 0) {
        #pragma unroll
        for (int i = 0; i < 8; i++) { mx[i] = 0.f; mn[i] = 0.f; }
    }
    #pragma unroll
    for (int i = 0; i < 8; i++) {
        int c = i * 32 + lane;
        if (c < C) { out[c] = tf32_rna(mx[i]); out[C + c] = tf32_rna(mn[i]); }
    }
}

// ---------------- K6b: pad + tf32-round weights ----------------
__global__ void k_prep_w(const float* __restrict__ w) {
    int i = blockIdx.x * blockDim.x + threadIdx.x;
    if (i >= 256 * C2) return;
    int r = i / C2;
    g_wr[i] = (r < C) ? tf32_rna(w[i]) : 0.f;
}

// ---------------- K7: tf32 mma.sync GEMM ----------------
// y[b, c, v] = sum_k w[c,k] * fea[b*R3+v, k]; CTA tile 128(M) x 128(N), K chunks of 32.
// smem per stage: A [128 rows x 128B] + B [128 rows x 128B], SW128-swizzled. 3 stages.
#define GSTAGES 3
#define NCHUNK 15
#define STAGE_BYTES 32768
#define SWZ(row, cb) (((row) << 7) + ((cb) ^ (((row) & 7) << 4)))

__global__ void __launch_bounds__(256) k_gemm_mma(const float* __restrict__ bias,
                                                  float* __restrict__ y) {
    extern __shared__ char smem[];
    uint32_t sbase = smem_u32(smem);
    int tid = threadIdx.x;
    int warp = tid >> 5, lane = tid & 31;
    int b = blockIdx.z;
    int c0 = blockIdx.y << 7;
    int v0 = blockIdx.x << 7;
    const float* fb = g_fea + ((size_t)b * R3 + v0) * C2;
    const float* wb = g_wr + (size_t)c0 * C2;

    int warp_m0 = (warp >> 2) << 6;      // 0 or 64
    int warp_n0 = (warp & 3) << 5;       // 0,32,64,96

    float acc[4][4][4];
    #pragma unroll
    for (int i = 0; i < 4; i++)
        #pragma unroll
        for (int j = 0; j < 4; j++)
            #pragma unroll
            for (int k = 0; k < 4; k++) acc[i][j][k] = 0.f;

    // loader: thread t handles row r = t>>1, 64B starting at (t&1)*64
    int lr = tid >> 1;
    int lj0 = (tid & 1) * 4;

    auto load_chunk = [&](int c, int s) {
        int k0 = c * 32;
        uint32_t sA = sbase + s * STAGE_BYTES;
        uint32_t sB = sA + 16384;
        const float* ga = wb + (size_t)lr * C2 + k0 + lj0 * 4;
        const float* gb = fb + (size_t)lr * C2 + k0 + lj0 * 4;
        #pragma unroll
        for (int jj = 0; jj < 4; jj++) {
            uint32_t off = SWZ((uint32_t)lr, (uint32_t)((lj0 + jj) * 16));
            cp_async16(sA + off, ga + jj * 4);
            cp_async16(sB + off, gb + jj * 4);
        }
    };

    #pragma unroll
    for (int s = 0; s < GSTAGES; s++) {
        load_chunk(s, s);
        asm volatile("cp.async.commit_group;" ::: "memory");
    }
    asm volatile("cp.async.wait_group 2;" ::: "memory");
    __syncthreads();

    for (int c = 0; c < NCHUNK; c++) {
        int s = c % GSTAGES;
        uint32_t sA = sbase + s * STAGE_BYTES;
        uint32_t sB = sA + 16384;
        #pragma unroll
        for (int ks = 0; ks < 4; ks++) {
            uint32_t a[4][4];
            #pragma unroll
            for (int mi = 0; mi < 4; mi++) {
                uint32_t row = (uint32_t)(warp_m0 + mi * 16 + (lane & 15));
                uint32_t cb = (uint32_t)(ks * 32 + ((lane >> 4) << 4));
                ldsm_x4(a[mi], sA + SWZ(row, cb));
            }
            uint32_t bf[2][4];
            #pragma unroll
            for (int p = 0; p < 2; p++) {
                uint32_t row = (uint32_t)(warp_n0 + p * 16 + (lane & 7) + ((lane >> 4) << 3));
                uint32_t cb = (uint32_t)(ks * 32 + (((lane >> 3) & 1) << 4));
                ldsm_x4(bf[p], sB + SWZ(row, cb));
            }
            #pragma unroll
            for (int mi = 0; mi < 4; mi++)
                #pragma unroll
                for (int nf = 0; nf < 4; nf++)
                    mma_tf32(acc[mi][nf], a[mi], bf[nf >> 1][(nf & 1) * 2],
                             bf[nf >> 1][(nf & 1) * 2 + 1]);
        }
        __syncthreads();
        if (c + GSTAGES < NCHUNK) load_chunk(c + GSTAGES, s);
        asm volatile("cp.async.commit_group;" ::: "memory");
        asm volatile("cp.async.wait_group 2;" ::: "memory");
        __syncthreads();
    }

    // epilogue
    #pragma unroll
    for (int mi = 0; mi < 4; mi++) {
        int ch0 = c0 + warp_m0 + mi * 16 + (lane >> 2);
        int ch1 = ch0 + 8;
        float bi0 = (ch0 < C) ? bias[ch0] : 0.f;
        float bi1 = (ch1 < C) ? bias[ch1] : 0.f;
        float* y0 = y + (((size_t)b * C + (ch0 < C ? ch0 : 0)) << 15);
        float* y1 = y + (((size_t)b * C + (ch1 < C ? ch1 : 0)) << 15);
        #pragma unroll
        for (int nf = 0; nf < 4; nf++) {
            int v = v0 + warp_n0 + nf * 8 + (lane & 3) * 2;
            if (ch0 < C) {
                float2 o = make_float2(acc[mi][nf][0] + bi0, acc[mi][nf][1] + bi0);
                *(float2*)(y0 + v) = o;
            }
            if (ch1 < C) {
                float2 o = make_float2(acc[mi][nf][2] + bi1, acc[mi][nf][3] + bi1);
                *(float2*)(y1 + v) = o;
            }
        }
    }
}

// ---------------- K8: BN batch stats per channel ----------------
__global__ void k_bnstats(const float* __restrict__ y, const float* __restrict__ gamma,
                          const float* __restrict__ beta) {
    int c = blockIdx.x;
    float s = 0.f, s2 = 0.f;
    const int TOT = NB * R3;
    for (int i = threadIdx.x; i < TOT; i += blockDim.x) {
        int b = i >> 15, v = i & (R3 - 1);
        float x = y[(((size_t)b * C + c) << 15) + v];
        s += x; s2 += x * x;
    }
    __shared__ float shs[32], shs2[32];
    int lane = threadIdx.x & 31, warp = threadIdx.x >> 5;
    #pragma unroll
    for (int o = 16; o; o >>= 1) {
        s  += __shfl_down_sync(0xffffffffu, s, o);
        s2 += __shfl_down_sync(0xffffffffu, s2, o);
    }
    if (lane == 0) { shs[warp] = s; shs2[warp] = s2; }
    __syncthreads();
    if (threadIdx.x == 0) {
        int nw = blockDim.x >> 5;
        float ts = 0.f, ts2 = 0.f;
        for (int i = 0; i < nw; i++) { ts += shs[i]; ts2 += shs2[i]; }
        float mean = ts / (float)TOT;
        float var = ts2 / (float)TOT - mean * mean;
        float rstd = rsqrtf(var + BN_EPS);
        float A = gamma[c] * rstd;
        g_bnA[c] = A;
        g_bnB[c] = beta[c] - mean * A;
    }
}

// ---------------- K9: fused BN + swish, in place ----------------
__global__ void k_bnswish(float* __restrict__ y) {
    size_t i4 = (size_t)blockIdx.x * blockDim.x + threadIdx.x;
    const size_t TOT4 = (size_t)NB * C * R3 / 4;
    if (i4 >= TOT4) return;
    size_t idx = i4 * 4;
    int c = (int)((idx >> 15) % C);
    float A = g_bnA[c], Bv = g_bnB[c];
    float4 v = *(float4*)(y + idx);
    float x0 = v.x * A + Bv, x1 = v.y * A + Bv, x2 = v.z * A + Bv, x3 = v.w * A + Bv;
    v.x = x0 / (1.f + expf(-x0));
    v.y = x1 / (1.f + expf(-x1));
    v.z = x2 / (1.f + expf(-x2));
    v.w = x3 / (1.f + expf(-x3));
    *(float4*)(y + idx) = v;
}

// ---------------- launch ----------------
extern "C" void kernel_launch(void* const* d_in, const int* in_sizes, int n_in,
                              void* d_out, int out_size) {
    const float* features = (const float*)d_in[0];
    const float* coords   = (const float*)d_in[1];
    const float* w        = (const float*)d_in[2];
    const float* bias     = (const float*)d_in[3];
    const float* gamma    = (const float*)d_in[4];
    const float* beta     = (const float*)d_in[5];
    float* out = (float*)d_out;

    const int Y_SIZE = NB * C * R3;
    const int NC_SIZE = NB * 3 * NP;
    int write_nc = (out_size >= Y_SIZE + NC_SIZE) ? 1 : 0;
    float* nc_out = out + Y_SIZE;

    const int GEMM_SMEM = GSTAGES * STAGE_BYTES;   // 96 KB
    static bool attr_set = false;
    if (!attr_set) {
        cudaFuncSetAttribute(k_gemm_mma, cudaFuncAttributeMaxDynamicSharedMemorySize,
                             GEMM_SMEM);
        attr_set = true;
    }

    k_coordstats<<<NB, 1024>>>(coords);
    k_zero_counts<<<(NVOX + 255) / 256, 256>>>();
    k_prep_w<<<(256 * C2 + 255) / 256, 256>>>(w);
    k_voxelize<<<(NB * NP + 255) / 256, 256>>>(coords, nc_out, write_nc);
    k_scan<<<NB, 1024>>>();
    k_scatter<<<(NB * NP + 255) / 256, 256>>>();
    {
        dim3 blk(32, 8);
        dim3 grd(NP / 32, (C + 31) / 32, NB);
        k_transpose<<<grd, blk>>>(features);
    }
    k_gather<<<(NVOX) / 8, 256>>>();
    {
        dim3 grd(R3 / 128, 2, NB);   // 256 x 2 x 4
        k_gemm_mma<<<grd, 256, GEMM_SMEM>>>(bias, out);
    }
    k_bnstats<<<C, 256>>>(out, gamma, beta);
    {
        size_t tot4 = (size_t)NB * C * R3 / 4;
        k_bnswish<<<(unsigned)((tot4 + 255) / 256), 256>>>(out);
    }
}

// round 7
// speedup vs baseline: 2.4465x; 1.1531x over previous
#include <cuda_runtime.h>
#include <math_constants.h>
#include <cstdint>

#define RR 32
#define R3 32768
#define C 240
#define C2 480
#define NB 4
#define NP 32768
#define NVOX (NB * R3)
#define BN_EPS 1e-5f

// ---------------- static scratch ----------------
__device__ float    g_csum[NB][3];
__device__ unsigned g_qmax[NB];
__device__ int   g_pos[NB * NP];
__device__ int   g_count[NVOX];
__device__ int   g_offset[NVOX];
__device__ int   g_plist[NB * NP];
__device__ float g_ft[(size_t)NB * NP * C];     // features transposed [B][N][C]
__device__ float g_fea[(size_t)NVOX * C2];      // voxel features [V][2C] (tf32-rounded)
__device__ float g_wr[256 * C2];                // weights padded to 256 rows, tf32-rounded
__device__ float g_sum[C];
__device__ float g_sum2[C];
__device__ float g_bnA[C];
__device__ float g_bnB[C];

// ---------------- helpers ----------------
__device__ __forceinline__ float tf32_rna(float x) {
    uint32_t u; asm("cvt.rna.tf32.f32 %0, %1;" : "=r"(u) : "f"(x));
    return __uint_as_float(u);
}
__device__ __forceinline__ uint32_t smem_u32(const void* p) {
    uint32_t a;
    asm("{ .reg .u64 t; cvta.to.shared.u64 t, %1; cvt.u32.u64 %0, t; }" : "=r"(a) : "l"(p));
    return a;
}
__device__ __forceinline__ void cp_async16(uint32_t dst, const void* src) {
    asm volatile("cp.async.cg.shared.global [%0], [%1], 16;" :: "r"(dst), "l"(src) : "memory");
}
__device__ __forceinline__ void ldsm_x4(uint32_t* r, uint32_t addr) {
    asm volatile("ldmatrix.sync.aligned.m8n8.x4.shared.b16 {%0,%1,%2,%3}, [%4];"
                 : "=r"(r[0]), "=r"(r[1]), "=r"(r[2]), "=r"(r[3]) : "r"(addr));
}
__device__ __forceinline__ void mma_tf32(float* c, const uint32_t* a, uint32_t b0, uint32_t b1) {
    asm volatile("mma.sync.aligned.m16n8k8.row.col.f32.tf32.tf32.f32 "
                 "{%0,%1,%2,%3}, {%4,%5,%6,%7}, {%8,%9}, {%0,%1,%2,%3};"
                 : "+f"(c[0]), "+f"(c[1]), "+f"(c[2]), "+f"(c[3])
                 : "r"(a[0]), "r"(a[1]), "r"(a[2]), "r"(a[3]), "r"(b0), "r"(b1));
}

// ---------------- K0: zero all per-replay state ----------------
__global__ void k_zero() {
    int i = blockIdx.x * blockDim.x + threadIdx.x;
    if (i < NVOX) g_count[i] = 0;
    if (i < C) { g_sum[i] = 0.f; g_sum2[i] = 0.f; }
    if (i < NB * 3) ((float*)g_csum)[i] = 0.f;
    if (i < NB) g_qmax[i] = 0u;
}

// ---------------- K1a: coord sum partials ----------------
__global__ void k_csum(const float* __restrict__ coords) {
    int b = blockIdx.y;
    int idx = blockIdx.x * blockDim.x + threadIdx.x;   // [0, NP/4)
    const float4* cx = (const float4*)(coords + (size_t)b * 3 * NP);
    float4 a = cx[idx];
    float4 c = cx[NP / 4 + idx];
    float4 d = cx[NP / 2 + idx];
    float sx = (a.x + a.y) + (a.z + a.w);
    float sy = (c.x + c.y) + (c.z + c.w);
    float sz = (d.x + d.y) + (d.z + d.w);
    __shared__ float sh[3][8];
    int lane = threadIdx.x & 31, warp = threadIdx.x >> 5;
    #pragma unroll
    for (int o = 16; o; o >>= 1) {
        sx += __shfl_down_sync(0xffffffffu, sx, o);
        sy += __shfl_down_sync(0xffffffffu, sy, o);
        sz += __shfl_down_sync(0xffffffffu, sz, o);
    }
    if (lane == 0) { sh[0][warp] = sx; sh[1][warp] = sy; sh[2][warp] = sz; }
    __syncthreads();
    if (threadIdx.x == 0) {
        float tx = 0.f, ty = 0.f, tz = 0.f;
        #pragma unroll
        for (int i = 0; i < 8; i++) { tx += sh[0][i]; ty += sh[1][i]; tz += sh[2][i]; }
        atomicAdd(&g_csum[b][0], tx);
        atomicAdd(&g_csum[b][1], ty);
        atomicAdd(&g_csum[b][2], tz);
    }
}

// ---------------- K1b: coord max-sq-norm partials ----------------
__global__ void k_cmax(const float* __restrict__ coords) {
    int b = blockIdx.y;
    int idx = blockIdx.x * blockDim.x + threadIdx.x;
    const float inv = 1.0f / (float)NP;
    float m0 = g_csum[b][0] * inv, m1 = g_csum[b][1] * inv, m2 = g_csum[b][2] * inv;
    const float4* cx = (const float4*)(coords + (size_t)b * 3 * NP);
    float4 a = cx[idx];
    float4 c = cx[NP / 4 + idx];
    float4 d = cx[NP / 2 + idx];
    float mx = 0.f, dx, dy, dz, q;
    dx = a.x - m0; dy = c.x - m1; dz = d.x - m2; q = dx*dx + dy*dy + dz*dz; mx = fmaxf(mx, q);
    dx = a.y - m0; dy = c.y - m1; dz = d.y - m2; q = dx*dx + dy*dy + dz*dz; mx = fmaxf(mx, q);
    dx = a.z - m0; dy = c.z - m1; dz = d.z - m2; q = dx*dx + dy*dy + dz*dz; mx = fmaxf(mx, q);
    dx = a.w - m0; dy = c.w - m1; dz = d.w - m2; q = dx*dx + dy*dy + dz*dz; mx = fmaxf(mx, q);
    __shared__ float sh[8];
    int lane = threadIdx.x & 31, warp = threadIdx.x >> 5;
    #pragma unroll
    for (int o = 16; o; o >>= 1) mx = fmaxf(mx, __shfl_down_sync(0xffffffffu, mx, o));
    if (lane == 0) sh[warp] = mx;
    __syncthreads();
    if (threadIdx.x == 0) {
        float t = 0.f;
        #pragma unroll
        for (int i = 0; i < 8; i++) t = fmaxf(t, sh[i]);
        atomicMax(&g_qmax[b], __float_as_uint(t));   // t >= 0: bit-order == float-order
    }
}

// ---------------- K2: nc + voxel id + count ----------------
__global__ void k_voxelize(const float* __restrict__ coords, float* __restrict__ nc_out,
                           int write_nc) {
    int i = blockIdx.x * blockDim.x + threadIdx.x;
    if (i >= NB * NP) return;
    int b = i >> 15, n = i & (NP - 1);
    const float* base = coords + (size_t)b * 3 * NP;
    float sc = sqrtf(__uint_as_float(g_qmax[b])) * 2.0f;
    const float inv = 1.0f / (float)NP;
    int vx[3];
    #pragma unroll
    for (int ch = 0; ch < 3; ch++) {
        float x = base[ch * NP + n];
        float u = (x - g_csum[b][ch] * inv) / sc + 0.5f;
        float t = fminf(fmaxf(u * (float)RR, 0.0f), (float)(RR - 1));
        if (write_nc) nc_out[((size_t)b * 3 + ch) * NP + n] = t;
        vx[ch] = (int)rintf(t);
    }
    int pos = vx[0] + vx[1] * RR + vx[2] * RR * RR;
    g_pos[i] = pos;
    atomicAdd(&g_count[(b << 15) + pos], 1);
}

// ---------------- K3: per-batch exclusive scan ----------------
__global__ void k_scan() {
    int b = blockIdx.x;
    int t = threadIdx.x;
    int base = b * R3 + t * 32;
    int4 v[8];
    const int4* src = (const int4*)(g_count + base);
    #pragma unroll
    for (int j = 0; j < 8; j++) v[j] = src[j];
    int s = 0;
    #pragma unroll
    for (int j = 0; j < 8; j++) s += v[j].x + v[j].y + v[j].z + v[j].w;
    __shared__ int warp_sums[32];
    int lane = t & 31, warp = t >> 5;
    int inc = s;
    #pragma unroll
    for (int o = 1; o < 32; o <<= 1) {
        int u = __shfl_up_sync(0xffffffffu, inc, o);
        if (lane >= o) inc += u;
    }
    if (lane == 31) warp_sums[warp] = inc;
    __syncthreads();
    if (warp == 0) {
        int w = warp_sums[lane];
        #pragma unroll
        for (int o = 1; o < 32; o <<= 1) {
            int u = __shfl_up_sync(0xffffffffu, w, o);
            if (lane >= o) w += u;
        }
        warp_sums[lane] = w;
    }
    __syncthreads();
    int run = inc - s + (warp ? warp_sums[warp - 1] : 0);
    int4* dst = (int4*)(g_offset + base);
    #pragma unroll
    for (int j = 0; j < 8; j++) {
        int4 o;
        o.x = run; run += v[j].x;
        o.y = run; run += v[j].y;
        o.z = run; run += v[j].z;
        o.w = run; run += v[j].w;
        dst[j] = o;
    }
}

// ---------------- K4: scatter (bumps g_offset; end = start + cnt) ----------------
__global__ void k_scatter() {
    int i = blockIdx.x * blockDim.x + threadIdx.x;
    if (i >= NB * NP) return;
    int b = i >> 15, n = i & (NP - 1);
    int pos = g_pos[i];
    int slot = atomicAdd(&g_offset[(b << 15) + pos], 1);
    g_plist[(b << 15) + slot] = n;
}

// ---------------- K5: transpose features [B,C,N] -> [B,N,C] ----------------
__global__ void k_transpose(const float* __restrict__ f) {
    __shared__ float tile[32][33];
    int b = blockIdx.z;
    int n0 = blockIdx.x * 32, c0 = blockIdx.y * 32;
    int n = n0 + threadIdx.x;
    for (int j = threadIdx.y; j < 32; j += 8) {
        int c = c0 + j;
        tile[j][threadIdx.x] = (c < C) ? f[((size_t)b * C + c) * NP + n] : 0.f;
    }
    __syncthreads();
    int c = c0 + threadIdx.x;
    if (c < C) {
        for (int j = threadIdx.y; j < 32; j += 8) {
            g_ft[((size_t)b * NP + n0 + j) * C + c] = tile[threadIdx.x][j];
        }
    }
}

// ---------------- K6: per-voxel max/min gather, tf32-rounded output ----------------
__global__ void k_gather() {
    int gw = (int)((blockIdx.x * (size_t)blockDim.x + threadIdx.x) >> 5);
    if (gw >= NVOX) return;
    int lane = threadIdx.x & 31;
    int b = gw >> 15;
    int idx = gw;
    int cnt = g_count[idx];
    int start = g_offset[idx] - cnt;
    float* out = g_fea + (size_t)idx * C2;
    float mx[8], mn[8];
    #pragma unroll
    for (int i = 0; i < 8; i++) { mx[i] = -CUDART_INF_F; mn[i] = CUDART_INF_F; }
    for (int p = 0; p < cnt; p++) {
        int n = g_plist[(b << 15) + start + p];
        const float* fp = g_ft + ((size_t)(b << 15) + n) * C;
        #pragma unroll
        for (int i = 0; i < 8; i++) {
            int c = i * 32 + lane;
            if (c < C) {
                float x = fp[c];
                mx[i] = fmaxf(mx[i], x);
                mn[i] = fminf(mn[i], x);
            }
        }
    }
    if (cnt == 0) {
        #pragma unroll
        for (int i = 0; i < 8; i++) { mx[i] = 0.f; mn[i] = 0.f; }
    }
    #pragma unroll
    for (int i = 0; i < 8; i++) {
        int c = i * 32 + lane;
        if (c < C) { out[c] = tf32_rna(mx[i]); out[C + c] = tf32_rna(mn[i]); }
    }
}

// ---------------- K6b: pad + tf32-round weights ----------------
__global__ void k_prep_w(const float* __restrict__ w) {
    int i = blockIdx.x * blockDim.x + threadIdx.x;
    if (i >= 256 * C2) return;
    int r = i / C2;
    g_wr[i] = (r < C) ? tf32_rna(w[i]) : 0.f;
}

// ---------------- K7: tf32 mma.sync GEMM, BN-stats fused in epilogue ----------------
#define GSTAGES 3
#define NCHUNK 15
#define STAGE_BYTES 32768
#define SWZ(row, cb) (((row) << 7) + ((cb) ^ (((row) & 7) << 4)))

__global__ void __launch_bounds__(256) k_gemm_mma(const float* __restrict__ bias,
                                                  float* __restrict__ y) {
    extern __shared__ char smem[];
    uint32_t sbase = smem_u32(smem);
    int tid = threadIdx.x;
    int warp = tid >> 5, lane = tid & 31;
    int b = blockIdx.z;
    int c0 = blockIdx.x << 7;          // c-tile fastest: wave-adjacent CTAs share B => L2 hit
    int v0 = blockIdx.y << 7;
    const float* fb = g_fea + ((size_t)b * R3 + v0) * C2;
    const float* wb = g_wr + (size_t)c0 * C2;

    int warp_m0 = (warp >> 2) << 6;
    int warp_n0 = (warp & 3) << 5;

    float acc[4][4][4];
    #pragma unroll
    for (int i = 0; i < 4; i++)
        #pragma unroll
        for (int j = 0; j < 4; j++)
            #pragma unroll
            for (int k = 0; k < 4; k++) acc[i][j][k] = 0.f;

    int lr = tid >> 1;
    int lj0 = (tid & 1) * 4;

    auto load_chunk = [&](int c, int s) {
        int k0 = c * 32;
        uint32_t sA = sbase + s * STAGE_BYTES;
        uint32_t sB = sA + 16384;
        const float* ga = wb + (size_t)lr * C2 + k0 + lj0 * 4;
        const float* gb = fb + (size_t)lr * C2 + k0 + lj0 * 4;
        #pragma unroll
        for (int jj = 0; jj < 4; jj++) {
            uint32_t off = SWZ((uint32_t)lr, (uint32_t)((lj0 + jj) * 16));
            cp_async16(sA + off, ga + jj * 4);
            cp_async16(sB + off, gb + jj * 4);
        }
    };

    #pragma unroll
    for (int s = 0; s < GSTAGES; s++) {
        load_chunk(s, s);
        asm volatile("cp.async.commit_group;" ::: "memory");
    }
    asm volatile("cp.async.wait_group 2;" ::: "memory");
    __syncthreads();

    for (int c = 0; c < NCHUNK; c++) {
        int s = c % GSTAGES;
        uint32_t sA = sbase + s * STAGE_BYTES;
        uint32_t sB = sA + 16384;
        #pragma unroll
        for (int ks = 0; ks < 4; ks++) {
            uint32_t a[4][4];
            #pragma unroll
            for (int mi = 0; mi < 4; mi++) {
                uint32_t row = (uint32_t)(warp_m0 + mi * 16 + (lane & 15));
                uint32_t cb = (uint32_t)(ks * 32 + ((lane >> 4) << 4));
                ldsm_x4(a[mi], sA + SWZ(row, cb));
            }
            uint32_t bf[2][4];
            #pragma unroll
            for (int p = 0; p < 2; p++) {
                uint32_t row = (uint32_t)(warp_n0 + p * 16 + (lane & 7) + ((lane >> 4) << 3));
                uint32_t cb = (uint32_t)(ks * 32 + (((lane >> 3) & 1) << 4));
                ldsm_x4(bf[p], sB + SWZ(row, cb));
            }
            #pragma unroll
            for (int mi = 0; mi < 4; mi++)
                #pragma unroll
                for (int nf = 0; nf < 4; nf++)
                    mma_tf32(acc[mi][nf], a[mi], bf[nf >> 1][(nf & 1) * 2],
                             bf[nf >> 1][(nf & 1) * 2 + 1]);
        }
        __syncthreads();
        if (c + GSTAGES < NCHUNK) load_chunk(c + GSTAGES, s);
        asm volatile("cp.async.commit_group;" ::: "memory");
        asm volatile("cp.async.wait_group 2;" ::: "memory");
        __syncthreads();
    }

    // epilogue: store y = acc + bias, and accumulate per-channel BN partials
    #pragma unroll
    for (int mi = 0; mi < 4; mi++) {
        int ch0 = c0 + warp_m0 + mi * 16 + (lane >> 2);
        int ch1 = ch0 + 8;
        float bi0 = (ch0 < C) ? bias[ch0] : 0.f;
        float bi1 = (ch1 < C) ? bias[ch1] : 0.f;
        float* y0 = y + (((size_t)b * C + (ch0 < C ? ch0 : 0)) << 15);
        float* y1 = y + (((size_t)b * C + (ch1 < C ? ch1 : 0)) << 15);
        float s0 = 0.f, q0 = 0.f, s1 = 0.f, q1 = 0.f;
        #pragma unroll
        for (int nf = 0; nf < 4; nf++) {
            int v = v0 + warp_n0 + nf * 8 + (lane & 3) * 2;
            float a0 = acc[mi][nf][0] + bi0, a1 = acc[mi][nf][1] + bi0;
            float a2 = acc[mi][nf][2] + bi1, a3 = acc[mi][nf][3] + bi1;
            if (ch0 < C) *(float2*)(y0 + v) = make_float2(a0, a1);
            if (ch1 < C) *(float2*)(y1 + v) = make_float2(a2, a3);
            s0 += a0 + a1; q0 += a0 * a0 + a1 * a1;
            s1 += a2 + a3; q1 += a2 * a2 + a3 * a3;
        }
        #pragma unroll
        for (int o = 1; o <= 2; o <<= 1) {           // reduce over quad (same channel row)
            s0 += __shfl_xor_sync(0xffffffffu, s0, o);
            q0 += __shfl_xor_sync(0xffffffffu, q0, o);
            s1 += __shfl_xor_sync(0xffffffffu, s1, o);
            q1 += __shfl_xor_sync(0xffffffffu, q1, o);
        }
        if ((lane & 3) == 0) {
            if (ch0 < C) { atomicAdd(&g_sum[ch0], s0); atomicAdd(&g_sum2[ch0], q0); }
            if (ch1 < C) { atomicAdd(&g_sum[ch1], s1); atomicAdd(&g_sum2[ch1], q1); }
        }
    }
}

// ---------------- K8: BN finalize (tiny) ----------------
__global__ void k_bnfin(const float* __restrict__ gamma, const float* __restrict__ beta) {
    int c = blockIdx.x * blockDim.x + threadIdx.x;
    if (c >= C) return;
    const float invT = 1.0f / (float)(NB * R3);
    float mean = g_sum[c] * invT;
    float var = g_sum2[c] * invT - mean * mean;
    float A = gamma[c] * rsqrtf(var + BN_EPS);
    g_bnA[c] = A;
    g_bnB[c] = beta[c] - mean * A;
}

// ---------------- K9: fused BN + swish, in place ----------------
__global__ void k_bnswish(float* __restrict__ y) {
    size_t i4 = (size_t)blockIdx.x * blockDim.x + threadIdx.x;
    const size_t TOT4 = (size_t)NB * C * R3 / 4;
    if (i4 >= TOT4) return;
    size_t idx = i4 * 4;
    int c = (int)((idx >> 15) % C);
    float A = g_bnA[c], Bv = g_bnB[c];
    float4 v = *(float4*)(y + idx);
    float x0 = v.x * A + Bv, x1 = v.y * A + Bv, x2 = v.z * A + Bv, x3 = v.w * A + Bv;
    v.x = x0 / (1.f + __expf(-x0));
    v.y = x1 / (1.f + __expf(-x1));
    v.z = x2 / (1.f + __expf(-x2));
    v.w = x3 / (1.f + __expf(-x3));
    *(float4*)(y + idx) = v;
}

// ---------------- launch ----------------
extern "C" void kernel_launch(void* const* d_in, const int* in_sizes, int n_in,
                              void* d_out, int out_size) {
    const float* features = (const float*)d_in[0];
    const float* coords   = (const float*)d_in[1];
    const float* w        = (const float*)d_in[2];
    const float* bias     = (const float*)d_in[3];
    const float* gamma    = (const float*)d_in[4];
    const float* beta     = (const float*)d_in[5];
    float* out = (float*)d_out;

    const int Y_SIZE = NB * C * R3;
    const int NC_SIZE = NB * 3 * NP;
    int write_nc = (out_size >= Y_SIZE + NC_SIZE) ? 1 : 0;
    float* nc_out = out + Y_SIZE;

    const int GEMM_SMEM = GSTAGES * STAGE_BYTES;   // 96 KB
    static bool attr_set = false;
    if (!attr_set) {
        cudaFuncSetAttribute(k_gemm_mma, cudaFuncAttributeMaxDynamicSharedMemorySize,
                             GEMM_SMEM);
        attr_set = true;
    }

    k_zero<<<(NVOX + 255) / 256, 256>>>();
    {
        dim3 grd(NP / 4 / 256, NB);
        k_csum<<<grd, 256>>>(coords);
        k_cmax<<<grd, 256>>>(coords);
    }
    k_prep_w<<<(256 * C2 + 255) / 256, 256>>>(w);
    k_voxelize<<<(NB * NP + 255) / 256, 256>>>(coords, nc_out, write_nc);
    k_scan<<<NB, 1024>>>();
    k_scatter<<<(NB * NP + 255) / 256, 256>>>();
    {
        dim3 blk(32, 8);
        dim3 grd(NP / 32, (C + 31) / 32, NB);
        k_transpose<<<grd, blk>>>(features);
    }
    k_gather<<<(NVOX) / 8, 256>>>();
    {
        dim3 grd(2, R3 / 128, NB);    // c-tile fastest for L2 B-reuse
        k_gemm_mma<<<grd, 256, GEMM_SMEM>>>(bias, out);
    }
    k_bnfin<<<1, 256>>>(gamma, beta);
    {
        size_t tot4 = (size_t)NB * C * R3 / 4;
        k_bnswish<<<(unsigned)((tot4 + 255) / 256), 256>>>(out);
    }
}

// round 8
// speedup vs baseline: 2.4567x; 1.0042x over previous
#include <cuda_runtime.h>
#include <math_constants.h>
#include <cstdint>

#define RR 32
#define R3 32768
#define C 240
#define C2 480
#define NB 4
#define NP 32768
#define NVOX (NB * R3)
#define BN_EPS 1e-5f

// ---------------- static scratch ----------------
__device__ float    g_cpart[128][3];    // per-block coord-sum partials
__device__ float    g_meanv[NB][3];
__device__ unsigned g_qmax[NB];
__device__ int   g_pos[NB * NP];
__device__ int   g_count[NVOX];
__device__ int   g_offset[NVOX];
__device__ int   g_plist[NB * NP];
__device__ float g_ft[(size_t)NB * NP * C];     // features transposed [B][N][C]
__device__ float g_fea[(size_t)NVOX * C2];      // voxel features [V][2C] (tf32-rounded)
__device__ float g_wr[256 * C2];                // weights padded, tf32-rounded
__device__ float g_sum[C];
__device__ float g_sum2[C];

// ---------------- helpers ----------------
__device__ __forceinline__ float tf32_rna(float x) {
    uint32_t u; asm("cvt.rna.tf32.f32 %0, %1;" : "=r"(u) : "f"(x));
    return __uint_as_float(u);
}
__device__ __forceinline__ uint32_t smem_u32(const void* p) {
    uint32_t a;
    asm("{ .reg .u64 t; cvta.to.shared.u64 t, %1; cvt.u32.u64 %0, t; }" : "=r"(a) : "l"(p));
    return a;
}
__device__ __forceinline__ void cp_async16(uint32_t dst, const void* src) {
    asm volatile("cp.async.cg.shared.global [%0], [%1], 16;" :: "r"(dst), "l"(src) : "memory");
}
__device__ __forceinline__ void ldsm_x4(uint32_t* r, uint32_t addr) {
    asm volatile("ldmatrix.sync.aligned.m8n8.x4.shared.b16 {%0,%1,%2,%3}, [%4];"
                 : "=r"(r[0]), "=r"(r[1]), "=r"(r[2]), "=r"(r[3]) : "r"(addr));
}
__device__ __forceinline__ void mma_tf32(float* c, const uint32_t* a, uint32_t b0, uint32_t b1) {
    asm volatile("mma.sync.aligned.m16n8k8.row.col.f32.tf32.tf32.f32 "
                 "{%0,%1,%2,%3}, {%4,%5,%6,%7}, {%8,%9}, {%0,%1,%2,%3};"
                 : "+f"(c[0]), "+f"(c[1]), "+f"(c[2]), "+f"(c[3])
                 : "r"(a[0]), "r"(a[1]), "r"(a[2]), "r"(a[3]), "r"(b0), "r"(b1));
}

// ---------------- K_setup: zero state + prep weights + coord-sum partials ----------------
// grid = 512 blocks x 256
__global__ void k_setup(const float* __restrict__ w, const float* __restrict__ coords) {
    int i = blockIdx.x * 256 + threadIdx.x;
    if (i < NVOX) g_count[i] = 0;
    if (i < C) { g_sum[i] = 0.f; g_sum2[i] = 0.f; }
    if (i < NB) g_qmax[i] = 0u;
    if (i < 256 * C2) {
        int r = i / C2;
        g_wr[i] = (r < C) ? tf32_rna(w[i]) : 0.f;
    }
    if (blockIdx.x < 128) {   // coord-sum partials: 32 blocks per batch
        int b = blockIdx.x >> 5;
        int idx = (blockIdx.x & 31) * 256 + threadIdx.x;   // [0, NP/4)
        const float4* cx = (const float4*)(coords + (size_t)b * 3 * NP);
        float4 a = cx[idx];
        float4 c = cx[NP / 4 + idx];
        float4 d = cx[NP / 2 + idx];
        float sx = (a.x + a.y) + (a.z + a.w);
        float sy = (c.x + c.y) + (c.z + c.w);
        float sz = (d.x + d.y) + (d.z + d.w);
        __shared__ float sh[3][8];
        int lane = threadIdx.x & 31, warp = threadIdx.x >> 5;
        #pragma unroll
        for (int o = 16; o; o >>= 1) {
            sx += __shfl_down_sync(0xffffffffu, sx, o);
            sy += __shfl_down_sync(0xffffffffu, sy, o);
            sz += __shfl_down_sync(0xffffffffu, sz, o);
        }
        if (lane == 0) { sh[0][warp] = sx; sh[1][warp] = sy; sh[2][warp] = sz; }
        __syncthreads();
        if (threadIdx.x == 0) {
            float tx = 0.f, ty = 0.f, tz = 0.f;
            #pragma unroll
            for (int j = 0; j < 8; j++) { tx += sh[0][j]; ty += sh[1][j]; tz += sh[2][j]; }
            g_cpart[blockIdx.x][0] = tx;
            g_cpart[blockIdx.x][1] = ty;
            g_cpart[blockIdx.x][2] = tz;
        }
    }
}

// ---------------- K_cmax: mean (from partials) + max-sq-norm partials ----------------
__global__ void k_cmax(const float* __restrict__ coords) {
    int b = blockIdx.y;
    __shared__ float mean_s[3];
    if (threadIdx.x < 3) {
        float s = 0.f;
        #pragma unroll
        for (int j = 0; j < 32; j++) s += g_cpart[(b << 5) + j][threadIdx.x];
        float m = s * (1.0f / (float)NP);
        mean_s[threadIdx.x] = m;
        if (blockIdx.x == 0) g_meanv[b][threadIdx.x] = m;
    }
    __syncthreads();
    float m0 = mean_s[0], m1 = mean_s[1], m2 = mean_s[2];
    int idx = blockIdx.x * blockDim.x + threadIdx.x;
    const float4* cx = (const float4*)(coords + (size_t)b * 3 * NP);
    float4 a = cx[idx];
    float4 c = cx[NP / 4 + idx];
    float4 d = cx[NP / 2 + idx];
    float mx = 0.f, dx, dy, dz, q;
    dx = a.x - m0; dy = c.x - m1; dz = d.x - m2; q = dx*dx + dy*dy + dz*dz; mx = fmaxf(mx, q);
    dx = a.y - m0; dy = c.y - m1; dz = d.y - m2; q = dx*dx + dy*dy + dz*dz; mx = fmaxf(mx, q);
    dx = a.z - m0; dy = c.z - m1; dz = d.z - m2; q = dx*dx + dy*dy + dz*dz; mx = fmaxf(mx, q);
    dx = a.w - m0; dy = c.w - m1; dz = d.w - m2; q = dx*dx + dy*dy + dz*dz; mx = fmaxf(mx, q);
    __shared__ float sh[8];
    int lane = threadIdx.x & 31, warp = threadIdx.x >> 5;
    #pragma unroll
    for (int o = 16; o; o >>= 1) mx = fmaxf(mx, __shfl_down_sync(0xffffffffu, mx, o));
    if (lane == 0) sh[warp] = mx;
    __syncthreads();
    if (threadIdx.x == 0) {
        float t = 0.f;
        #pragma unroll
        for (int j = 0; j < 8; j++) t = fmaxf(t, sh[j]);
        atomicMax(&g_qmax[b], __float_as_uint(t));   // t >= 0
    }
}

// ---------------- K2: nc + voxel id + count ----------------
__global__ void k_voxelize(const float* __restrict__ coords, float* __restrict__ nc_out,
                           int write_nc) {
    int i = blockIdx.x * blockDim.x + threadIdx.x;
    if (i >= NB * NP) return;
    int b = i >> 15, n = i & (NP - 1);
    const float* base = coords + (size_t)b * 3 * NP;
    float sc = sqrtf(__uint_as_float(g_qmax[b])) * 2.0f;
    int vx[3];
    #pragma unroll
    for (int ch = 0; ch < 3; ch++) {
        float x = base[ch * NP + n];
        float u = (x - g_meanv[b][ch]) / sc + 0.5f;
        float t = fminf(fmaxf(u * (float)RR, 0.0f), (float)(RR - 1));
        if (write_nc) nc_out[((size_t)b * 3 + ch) * NP + n] = t;
        vx[ch] = (int)rintf(t);
    }
    int pos = vx[0] + vx[1] * RR + vx[2] * RR * RR;
    g_pos[i] = pos;
    atomicAdd(&g_count[(b << 15) + pos], 1);
}

// ---------------- K3: per-batch exclusive scan ----------------
__global__ void k_scan() {
    int b = blockIdx.x;
    int t = threadIdx.x;
    int base = b * R3 + t * 32;
    int4 v[8];
    const int4* src = (const int4*)(g_count + base);
    #pragma unroll
    for (int j = 0; j < 8; j++) v[j] = src[j];
    int s = 0;
    #pragma unroll
    for (int j = 0; j < 8; j++) s += v[j].x + v[j].y + v[j].z + v[j].w;
    __shared__ int warp_sums[32];
    int lane = t & 31, warp = t >> 5;
    int inc = s;
    #pragma unroll
    for (int o = 1; o < 32; o <<= 1) {
        int u = __shfl_up_sync(0xffffffffu, inc, o);
        if (lane >= o) inc += u;
    }
    if (lane == 31) warp_sums[warp] = inc;
    __syncthreads();
    if (warp == 0) {
        int w = warp_sums[lane];
        #pragma unroll
        for (int o = 1; o < 32; o <<= 1) {
            int u = __shfl_up_sync(0xffffffffu, w, o);
            if (lane >= o) w += u;
        }
        warp_sums[lane] = w;
    }
    __syncthreads();
    int run = inc - s + (warp ? warp_sums[warp - 1] : 0);
    int4* dst = (int4*)(g_offset + base);
    #pragma unroll
    for (int j = 0; j < 8; j++) {
        int4 o;
        o.x = run; run += v[j].x;
        o.y = run; run += v[j].y;
        o.z = run; run += v[j].z;
        o.w = run; run += v[j].w;
        dst[j] = o;
    }
}

// ---------------- K4: scatter (bumps g_offset; end = start + cnt) ----------------
__global__ void k_scatter() {
    int i = blockIdx.x * blockDim.x + threadIdx.x;
    if (i >= NB * NP) return;
    int b = i >> 15, n = i & (NP - 1);
    int pos = g_pos[i];
    int slot = atomicAdd(&g_offset[(b << 15) + pos], 1);
    g_plist[(b << 15) + slot] = n;
}

// ---------------- K5: transpose features [B,C,N] -> [B,N,C] (runs on side stream) ----------------
__global__ void k_transpose(const float* __restrict__ f) {
    __shared__ float tile[32][33];
    int b = blockIdx.z;
    int n0 = blockIdx.x * 32, c0 = blockIdx.y * 32;
    int n = n0 + threadIdx.x;
    for (int j = threadIdx.y; j < 32; j += 8) {
        int c = c0 + j;
        tile[j][threadIdx.x] = (c < C) ? f[((size_t)b * C + c) * NP + n] : 0.f;
    }
    __syncthreads();
    int c = c0 + threadIdx.x;
    if (c < C) {
        for (int j = threadIdx.y; j < 32; j += 8) {
            g_ft[((size_t)b * NP + n0 + j) * C + c] = tile[threadIdx.x][j];
        }
    }
}

// ---------------- K6: per-voxel max/min gather, tf32-rounded output ----------------
__global__ void k_gather() {
    int gw = (int)((blockIdx.x * (size_t)blockDim.x + threadIdx.x) >> 5);
    if (gw >= NVOX) return;
    int lane = threadIdx.x & 31;
    int b = gw >> 15;
    int idx = gw;
    int cnt = g_count[idx];
    int start = g_offset[idx] - cnt;
    float* out = g_fea + (size_t)idx * C2;
    float mx[8], mn[8];
    #pragma unroll
    for (int i = 0; i < 8; i++) { mx[i] = -CUDART_INF_F; mn[i] = CUDART_INF_F; }
    for (int p = 0; p < cnt; p++) {
        int n = g_plist[(b << 15) + start + p];
        const float* fp = g_ft + ((size_t)(b << 15) + n) * C;
        #pragma unroll
        for (int i = 0; i < 8; i++) {
            int c = i * 32 + lane;
            if (c < C) {
                float x = fp[c];
                mx[i] = fmaxf(mx[i], x);
                mn[i] = fminf(mn[i], x);
            }
        }
    }
    if (cnt == 0) {
        #pragma unroll
        for (int i = 0; i < 8; i++) { mx[i] = 0.f; mn[i] = 0.f; }
    }
    #pragma unroll
    for (int i = 0; i < 8; i++) {
        int c = i * 32 + lane;
        if (c < C) { out[c] = tf32_rna(mx[i]); out[C + c] = tf32_rna(mn[i]); }
    }
}

// ---------------- K7: tf32 mma.sync GEMM, BN-stats fused in epilogue ----------------
#define GSTAGES 3
#define NCHUNK 15
#define STAGE_BYTES 32768
#define SWZ(row, cb) (((row) << 7) + ((cb) ^ (((row) & 7) << 4)))

__global__ void __launch_bounds__(256) k_gemm_mma(const float* __restrict__ bias,
                                                  float* __restrict__ y) {
    extern __shared__ char smem[];
    uint32_t sbase = smem_u32(smem);
    int tid = threadIdx.x;
    int warp = tid >> 5, lane = tid & 31;
    int b = blockIdx.z;
    int c0 = blockIdx.x << 7;          // c-tile fastest: wave-adjacent CTAs share B => L2 hit
    int v0 = blockIdx.y << 7;
    const float* fb = g_fea + ((size_t)b * R3 + v0) * C2;
    const float* wb = g_wr + (size_t)c0 * C2;

    int warp_m0 = (warp >> 2) << 6;
    int warp_n0 = (warp & 3) << 5;

    float acc[4][4][4];
    #pragma unroll
    for (int i = 0; i < 4; i++)
        #pragma unroll
        for (int j = 0; j < 4; j++)
            #pragma unroll
            for (int k = 0; k < 4; k++) acc[i][j][k] = 0.f;

    int lr = tid >> 1;
    int lj0 = (tid & 1) * 4;

    auto load_chunk = [&](int c, int s) {
        int k0 = c * 32;
        uint32_t sA = sbase + s * STAGE_BYTES;
        uint32_t sB = sA + 16384;
        const float* ga = wb + (size_t)lr * C2 + k0 + lj0 * 4;
        const float* gb = fb + (size_t)lr * C2 + k0 + lj0 * 4;
        #pragma unroll
        for (int jj = 0; jj < 4; jj++) {
            uint32_t off = SWZ((uint32_t)lr, (uint32_t)((lj0 + jj) * 16));
            cp_async16(sA + off, ga + jj * 4);
            cp_async16(sB + off, gb + jj * 4);
        }
    };

    #pragma unroll
    for (int s = 0; s < GSTAGES; s++) {
        load_chunk(s, s);
        asm volatile("cp.async.commit_group;" ::: "memory");
    }
    asm volatile("cp.async.wait_group 2;" ::: "memory");
    __syncthreads();

    for (int c = 0; c < NCHUNK; c++) {
        int s = c % GSTAGES;
        uint32_t sA = sbase + s * STAGE_BYTES;
        uint32_t sB = sA + 16384;
        #pragma unroll
        for (int ks = 0; ks < 4; ks++) {
            uint32_t a[4][4];
            #pragma unroll
            for (int mi = 0; mi < 4; mi++) {
                uint32_t row = (uint32_t)(warp_m0 + mi * 16 + (lane & 15));
                uint32_t cb = (uint32_t)(ks * 32 + ((lane >> 4) << 4));
                ldsm_x4(a[mi], sA + SWZ(row, cb));
            }
            uint32_t bf[2][4];
            #pragma unroll
            for (int p = 0; p < 2; p++) {
                uint32_t row = (uint32_t)(warp_n0 + p * 16 + (lane & 7) + ((lane >> 4) << 3));
                uint32_t cb = (uint32_t)(ks * 32 + (((lane >> 3) & 1) << 4));
                ldsm_x4(bf[p], sB + SWZ(row, cb));
            }
            #pragma unroll
            for (int mi = 0; mi < 4; mi++)
                #pragma unroll
                for (int nf = 0; nf < 4; nf++)
                    mma_tf32(acc[mi][nf], a[mi], bf[nf >> 1][(nf & 1) * 2],
                             bf[nf >> 1][(nf & 1) * 2 + 1]);
        }
        __syncthreads();
        if (c + GSTAGES < NCHUNK) load_chunk(c + GSTAGES, s);
        asm volatile("cp.async.commit_group;" ::: "memory");
        asm volatile("cp.async.wait_group 2;" ::: "memory");
        __syncthreads();
    }

    // epilogue: store y = acc + bias, accumulate per-channel BN partials
    #pragma unroll
    for (int mi = 0; mi < 4; mi++) {
        int ch0 = c0 + warp_m0 + mi * 16 + (lane >> 2);
        int ch1 = ch0 + 8;
        float bi0 = (ch0 < C) ? bias[ch0] : 0.f;
        float bi1 = (ch1 < C) ? bias[ch1] : 0.f;
        float* y0 = y + (((size_t)b * C + (ch0 < C ? ch0 : 0)) << 15);
        float* y1 = y + (((size_t)b * C + (ch1 < C ? ch1 : 0)) << 15);
        float s0 = 0.f, q0 = 0.f, s1 = 0.f, q1 = 0.f;
        #pragma unroll
        for (int nf = 0; nf < 4; nf++) {
            int v = v0 + warp_n0 + nf * 8 + (lane & 3) * 2;
            float a0 = acc[mi][nf][0] + bi0, a1 = acc[mi][nf][1] + bi0;
            float a2 = acc[mi][nf][2] + bi1, a3 = acc[mi][nf][3] + bi1;
            if (ch0 < C) *(float2*)(y0 + v) = make_float2(a0, a1);
            if (ch1 < C) *(float2*)(y1 + v) = make_float2(a2, a3);
            s0 += a0 + a1; q0 += a0 * a0 + a1 * a1;
            s1 += a2 + a3; q1 += a2 * a2 + a3 * a3;
        }
        #pragma unroll
        for (int o = 1; o <= 2; o <<= 1) {
            s0 += __shfl_xor_sync(0xffffffffu, s0, o);
            q0 += __shfl_xor_sync(0xffffffffu, q0, o);
            s1 += __shfl_xor_sync(0xffffffffu, s1, o);
            q1 += __shfl_xor_sync(0xffffffffu, q1, o);
        }
        if ((lane & 3) == 0) {
            if (ch0 < C) { atomicAdd(&g_sum[ch0], s0); atomicAdd(&g_sum2[ch0], q0); }
            if (ch1 < C) { atomicAdd(&g_sum[ch1], s1); atomicAdd(&g_sum2[ch1], q1); }
        }
    }
}

// ---------------- K9: fused BN-finalize + BN + swish, in place ----------------
__global__ void k_bnswish(float* __restrict__ y, const float* __restrict__ gamma,
                          const float* __restrict__ beta) {
    size_t i4 = (size_t)blockIdx.x * blockDim.x + threadIdx.x;
    const size_t TOT4 = (size_t)NB * C * R3 / 4;
    if (i4 >= TOT4) return;
    size_t idx = i4 * 4;
    int c = (int)((idx >> 15) % C);   // one c per block (block spans 1024 floats < 32768)
    const float invT = 1.0f / (float)(NB * R3);
    float mean = g_sum[c] * invT;
    float var = g_sum2[c] * invT - mean * mean;
    float A = gamma[c] * rsqrtf(var + BN_EPS);
    float Bv = beta[c] - mean * A;
    float4 v = *(float4*)(y + idx);
    float x0 = v.x * A + Bv, x1 = v.y * A + Bv, x2 = v.z * A + Bv, x3 = v.w * A + Bv;
    v.x = x0 / (1.f + __expf(-x0));
    v.y = x1 / (1.f + __expf(-x1));
    v.z = x2 / (1.f + __expf(-x2));
    v.w = x3 / (1.f + __expf(-x3));
    *(float4*)(y + idx) = v;
}

// ---------------- launch ----------------
extern "C" void kernel_launch(void* const* d_in, const int* in_sizes, int n_in,
                              void* d_out, int out_size) {
    const float* features = (const float*)d_in[0];
    const float* coords   = (const float*)d_in[1];
    const float* w        = (const float*)d_in[2];
    const float* bias     = (const float*)d_in[3];
    const float* gamma    = (const float*)d_in[4];
    const float* beta     = (const float*)d_in[5];
    float* out = (float*)d_out;

    const int Y_SIZE = NB * C * R3;
    const int NC_SIZE = NB * 3 * NP;
    int write_nc = (out_size >= Y_SIZE + NC_SIZE) ? 1 : 0;
    float* nc_out = out + Y_SIZE;

    const int GEMM_SMEM = GSTAGES * STAGE_BYTES;   // 96 KB
    static cudaStream_t s1 = nullptr;
    static cudaEvent_t evA = nullptr, evT = nullptr;
    if (!s1) {
        cudaFuncSetAttribute(k_gemm_mma, cudaFuncAttributeMaxDynamicSharedMemorySize,
                             GEMM_SMEM);
        cudaStreamCreateWithFlags(&s1, cudaStreamNonBlocking);
        cudaEventCreateWithFlags(&evA, cudaEventDisableTiming);
        cudaEventCreateWithFlags(&evT, cudaEventDisableTiming);
    }

    // fork: transpose runs on s1, overlapping the voxel chain on the main stream
    cudaEventRecord(evA, 0);
    cudaStreamWaitEvent(s1, evA, 0);
    {
        dim3 blk(32, 8);
        dim3 grd(NP / 32, (C + 31) / 32, NB);
        k_transpose<<<grd, blk, 0, s1>>>(features);
    }
    cudaEventRecord(evT, s1);

    // main chain
    k_setup<<<512, 256>>>(w, coords);
    {
        dim3 grd(NP / 4 / 256, NB);
        k_cmax<<<grd, 256>>>(coords);
    }
    k_voxelize<<<(NB * NP + 255) / 256, 256>>>(coords, nc_out, write_nc);
    k_scan<<<NB, 1024>>>();
    k_scatter<<<(NB * NP + 255) / 256, 256>>>();

    // join: gather needs both scatter (main) and transpose (s1)
    cudaStreamWaitEvent(0, evT, 0);
    k_gather<<<(NVOX) / 8, 256>>>();
    {
        dim3 grd(2, R3 / 128, NB);
        k_gemm_mma<<<grd, 256, GEMM_SMEM>>>(bias, out);
    }
    {
        size_t tot4 = (size_t)NB * C * R3 / 4;
        k_bnswish<<<(unsigned)((tot4 + 255) / 256), 256>>>(out, gamma, beta);
    }
}

// round 10
// speedup vs baseline: 4.4277x; 1.8023x over previous
#include <cuda_runtime.h>
#include <math_constants.h>
#include <cstdint>

#define RR 32
#define R3 32768
#define C 240
#define C2 480
#define NB 4
#define NP 32768
#define NVOX (NB * R3)
#define NOCCMAX 131072
#define BN_EPS 1e-5f

// ---------------- static scratch ----------------
__device__ float    g_cpart[128][3];
__device__ float    g_meanv[NB][3];
__device__ unsigned g_qmax[NB];
__device__ int   g_pos[NB * NP];
__device__ int   g_count[NVOX];
__device__ int   g_offset[NVOX];
__device__ int   g_gidx[NVOX];          // compact index per voxel, -1 if empty
__device__ int   g_boc[NB];             // occupied count per batch
__device__ int   g_plist[NB * NP];
__device__ float g_ft[(size_t)NB * NP * C];     // features transposed [B][N][C]
__device__ float g_fea[(size_t)NVOX * C2];      // COMPACT voxel features [gidx][2C]
__device__ float g_yc[(size_t)C * NOCCMAX];     // COMPACT gemm output [c][gidx] (incl bias)
__device__ float g_wr[256 * C2];
__device__ float g_sum[C];
__device__ float g_sum2[C];

// ---------------- helpers ----------------
__device__ __forceinline__ float tf32_rna(float x) {
    uint32_t u; asm("cvt.rna.tf32.f32 %0, %1;" : "=r"(u) : "f"(x));
    return __uint_as_float(u);
}
__device__ __forceinline__ uint32_t smem_u32(const void* p) {
    uint32_t a;
    asm("{ .reg .u64 t; cvta.to.shared.u64 t, %1; cvt.u32.u64 %0, t; }" : "=r"(a) : "l"(p));
    return a;
}
__device__ __forceinline__ void cp_async16(uint32_t dst, const void* src) {
    asm volatile("cp.async.cg.shared.global [%0], [%1], 16;" :: "r"(dst), "l"(src) : "memory");
}
__device__ __forceinline__ void ldsm_x4(uint32_t* r, uint32_t addr) {
    asm volatile("ldmatrix.sync.aligned.m8n8.x4.shared.b16 {%0,%1,%2,%3}, [%4];"
                 : "=r"(r[0]), "=r"(r[1]), "=r"(r[2]), "=r"(r[3]) : "r"(addr));
}
__device__ __forceinline__ void mma_tf32(float* c, const uint32_t* a, uint32_t b0, uint32_t b1) {
    asm volatile("mma.sync.aligned.m16n8k8.row.col.f32.tf32.tf32.f32 "
                 "{%0,%1,%2,%3}, {%4,%5,%6,%7}, {%8,%9}, {%0,%1,%2,%3};"
                 : "+f"(c[0]), "+f"(c[1]), "+f"(c[2]), "+f"(c[3])
                 : "r"(a[0]), "r"(a[1]), "r"(a[2]), "r"(a[3]), "r"(b0), "r"(b1));
}

// ---------------- K_setup: zero state + prep weights + coord-sum partials ----------------
__global__ void __launch_bounds__(256) k_setup(const float* __restrict__ w,
                                               const float* __restrict__ coords) {
    int i = blockIdx.x * 256 + threadIdx.x;
    if (i < NVOX) g_count[i] = 0;
    if (i < C) { g_sum[i] = 0.f; g_sum2[i] = 0.f; }
    if (i < NB) g_qmax[i] = 0u;
    if (i < 256 * C2) {
        int r = i / C2;
        g_wr[i] = (r < C) ? tf32_rna(w[i]) : 0.f;
    }
    if (blockIdx.x < 128) {
        int b = blockIdx.x >> 5;
        int idx = (blockIdx.x & 31) * 256 + threadIdx.x;
        const float4* cx = (const float4*)(coords + (size_t)b * 3 * NP);
        float4 a = cx[idx];
        float4 c = cx[NP / 4 + idx];
        float4 d = cx[NP / 2 + idx];
        float sx = (a.x + a.y) + (a.z + a.w);
        float sy = (c.x + c.y) + (c.z + c.w);
        float sz = (d.x + d.y) + (d.z + d.w);
        __shared__ float sh[3][8];
        int lane = threadIdx.x & 31, warp = threadIdx.x >> 5;
        #pragma unroll
        for (int o = 16; o; o >>= 1) {
            sx += __shfl_down_sync(0xffffffffu, sx, o);
            sy += __shfl_down_sync(0xffffffffu, sy, o);
            sz += __shfl_down_sync(0xffffffffu, sz, o);
        }
        if (lane == 0) { sh[0][warp] = sx; sh[1][warp] = sy; sh[2][warp] = sz; }
        __syncthreads();
        if (threadIdx.x == 0) {
            float tx = 0.f, ty = 0.f, tz = 0.f;
            #pragma unroll
            for (int j = 0; j < 8; j++) { tx += sh[0][j]; ty += sh[1][j]; tz += sh[2][j]; }
            g_cpart[blockIdx.x][0] = tx;
            g_cpart[blockIdx.x][1] = ty;
            g_cpart[blockIdx.x][2] = tz;
        }
    }
}

// ---------------- K_cmax ----------------
__global__ void __launch_bounds__(256) k_cmax(const float* __restrict__ coords) {
    int b = blockIdx.y;
    __shared__ float mean_s[3];
    if (threadIdx.x < 3) {
        float s = 0.f;
        #pragma unroll
        for (int j = 0; j < 32; j++) s += g_cpart[(b << 5) + j][threadIdx.x];
        float m = s * (1.0f / (float)NP);
        mean_s[threadIdx.x] = m;
        if (blockIdx.x == 0) g_meanv[b][threadIdx.x] = m;
    }
    __syncthreads();
    float m0 = mean_s[0], m1 = mean_s[1], m2 = mean_s[2];
    int idx = blockIdx.x * blockDim.x + threadIdx.x;
    const float4* cx = (const float4*)(coords + (size_t)b * 3 * NP);
    float4 a = cx[idx];
    float4 c = cx[NP / 4 + idx];
    float4 d = cx[NP / 2 + idx];
    float mx = 0.f, dx, dy, dz, q;
    dx = a.x - m0; dy = c.x - m1; dz = d.x - m2; q = dx*dx + dy*dy + dz*dz; mx = fmaxf(mx, q);
    dx = a.y - m0; dy = c.y - m1; dz = d.y - m2; q = dx*dx + dy*dy + dz*dz; mx = fmaxf(mx, q);
    dx = a.z - m0; dy = c.z - m1; dz = d.z - m2; q = dx*dx + dy*dy + dz*dz; mx = fmaxf(mx, q);
    dx = a.w - m0; dy = c.w - m1; dz = d.w - m2; q = dx*dx + dy*dy + dz*dz; mx = fmaxf(mx, q);
    __shared__ float sh[8];
    int lane = threadIdx.x & 31, warp = threadIdx.x >> 5;
    #pragma unroll
    for (int o = 16; o; o >>= 1) mx = fmaxf(mx, __shfl_down_sync(0xffffffffu, mx, o));
    if (lane == 0) sh[warp] = mx;
    __syncthreads();
    if (threadIdx.x == 0) {
        float t = 0.f;
        #pragma unroll
        for (int j = 0; j < 8; j++) t = fmaxf(t, sh[j]);
        atomicMax(&g_qmax[b], __float_as_uint(t));
    }
}

// ---------------- K2: nc + voxel id + count ----------------
__global__ void __launch_bounds__(256) k_voxelize(const float* __restrict__ coords,
                                                  float* __restrict__ nc_out, int write_nc) {
    int i = blockIdx.x * blockDim.x + threadIdx.x;
    if (i >= NB * NP) return;
    int b = i >> 15, n = i & (NP - 1);
    const float* base = coords + (size_t)b * 3 * NP;
    float sc = sqrtf(__uint_as_float(g_qmax[b])) * 2.0f;
    int vx[3];
    #pragma unroll
    for (int ch = 0; ch < 3; ch++) {
        float x = base[ch * NP + n];
        float u = (x - g_meanv[b][ch]) / sc + 0.5f;
        float t = fminf(fmaxf(u * (float)RR, 0.0f), (float)(RR - 1));
        if (write_nc) nc_out[((size_t)b * 3 + ch) * NP + n] = t;
        vx[ch] = (int)rintf(t);
    }
    int pos = vx[0] + vx[1] * RR + vx[2] * RR * RR;
    g_pos[i] = pos;
    atomicAdd(&g_count[(b << 15) + pos], 1);
}

// ---------------- K3: per-batch dual scan (points + occupancy), reg-capped ----------------
// packed: high 16 bits = point count, low 16 bits = occupancy (both <= 32768)
__global__ void __launch_bounds__(1024) k_scan() {
    int b = blockIdx.x;
    int t = threadIdx.x;
    int base = b * R3 + t * 32;
    int4 v[8];
    const int4* src = (const int4*)(g_count + base);
    #pragma unroll
    for (int j = 0; j < 8; j++) v[j] = src[j];
    unsigned comb = 0;
    #pragma unroll
    for (int j = 0; j < 8; j++) {
        comb += ((unsigned)(v[j].x) << 16) + (v[j].x > 0);
        comb += ((unsigned)(v[j].y) << 16) + (v[j].y > 0);
        comb += ((unsigned)(v[j].z) << 16) + (v[j].z > 0);
        comb += ((unsigned)(v[j].w) << 16) + (v[j].w > 0);
    }
    __shared__ unsigned warp_sums[32];
    int lane = t & 31, warp = t >> 5;
    unsigned inc = comb;
    #pragma unroll
    for (int o = 1; o < 32; o <<= 1) {
        unsigned u = __shfl_up_sync(0xffffffffu, inc, o);
        if (lane >= o) inc += u;
    }
    if (lane == 31) warp_sums[warp] = inc;
    __syncthreads();
    if (warp == 0) {
        unsigned w = warp_sums[lane];
        #pragma unroll
        for (int o = 1; o < 32; o <<= 1) {
            unsigned u = __shfl_up_sync(0xffffffffu, w, o);
            if (lane >= o) w += u;
        }
        warp_sums[lane] = w;
    }
    __syncthreads();
    unsigned excl = inc - comb + (warp ? warp_sums[warp - 1] : 0u);
    int run_pts = (int)(excl >> 16);
    int run_occ = (int)(excl & 0xFFFFu);
    int4* dsto = (int4*)(g_offset + base);
    int4* dstg = (int4*)(g_gidx + base);
    #pragma unroll
    for (int j = 0; j < 8; j++) {
        int4 o, g;
        o.x = run_pts; g.x = (v[j].x > 0) ? run_occ : -1; run_pts += v[j].x; run_occ += (v[j].x > 0);
        o.y = run_pts; g.y = (v[j].y > 0) ? run_occ : -1; run_pts += v[j].y; run_occ += (v[j].y > 0);
        o.z = run_pts; g.z = (v[j].z > 0) ? run_occ : -1; run_pts += v[j].z; run_occ += (v[j].z > 0);
        o.w = run_pts; g.w = (v[j].w > 0) ? run_occ : -1; run_pts += v[j].w; run_occ += (v[j].w > 0);
        dsto[j] = o;
        dstg[j] = g;
    }
    if (t == 1023) g_boc[b] = run_occ;
}

// ---------------- K4: scatter ----------------
__global__ void __launch_bounds__(256) k_scatter() {
    int i = blockIdx.x * blockDim.x + threadIdx.x;
    if (i >= NB * NP) return;
    int b = i >> 15, n = i & (NP - 1);
    int pos = g_pos[i];
    int slot = atomicAdd(&g_offset[(b << 15) + pos], 1);
    g_plist[(b << 15) + slot] = n;
}

// ---------------- K5: transpose [B,C,N] -> [B,N,C] (side stream) ----------------
__global__ void __launch_bounds__(256) k_transpose(const float* __restrict__ f) {
    __shared__ float tile[32][33];
    int b = blockIdx.z;
    int n0 = blockIdx.x * 32, c0 = blockIdx.y * 32;
    int n = n0 + threadIdx.x;
    for (int j = threadIdx.y; j < 32; j += 8) {
        int c = c0 + j;
        tile[j][threadIdx.x] = (c < C) ? f[((size_t)b * C + c) * NP + n] : 0.f;
    }
    __syncthreads();
    int c = c0 + threadIdx.x;
    if (c < C) {
        for (int j = threadIdx.y; j < 32; j += 8) {
            g_ft[((size_t)b * NP + n0 + j) * C + c] = tile[threadIdx.x][j];
        }
    }
}

// ---------------- K6: gather into COMPACT fea (occupied voxels only) ----------------
__global__ void __launch_bounds__(256) k_gather() {
    int gw = (int)((blockIdx.x * (size_t)blockDim.x + threadIdx.x) >> 5);
    if (gw >= NVOX) return;
    int idx = gw;
    int cnt = g_count[idx];
    if (cnt == 0) return;
    int lane = threadIdx.x & 31;
    int b = gw >> 15;
    int pb = 0;
    for (int j = 0; j < NB; j++) pb += (j < b) ? g_boc[j] : 0;
    int gi = g_gidx[idx] + pb;
    int start = g_offset[idx] - cnt;
    float* out = g_fea + (size_t)gi * C2;
    float mx[8], mn[8];
    #pragma unroll
    for (int i = 0; i < 8; i++) { mx[i] = -CUDART_INF_F; mn[i] = CUDART_INF_F; }
    for (int p = 0; p < cnt; p++) {
        int n = g_plist[(b << 15) + start + p];
        const float* fp = g_ft + ((size_t)(b << 15) + n) * C;
        #pragma unroll
        for (int i = 0; i < 8; i++) {
            int c = i * 32 + lane;
            if (c < C) {
                float x = fp[c];
                mx[i] = fmaxf(mx[i], x);
                mn[i] = fminf(mn[i], x);
            }
        }
    }
    #pragma unroll
    for (int i = 0; i < 8; i++) {
        int c = i * 32 + lane;
        if (c < C) { out[c] = tf32_rna(mx[i]); out[C + c] = tf32_rna(mn[i]); }
    }
}

// ---------------- K7: tf32 mma GEMM over compact columns, BN-stats fused ----------------
#define GSTAGES 3
#define NCHUNK 15
#define STAGE_BYTES 32768
#define SWZ(row, cb) (((row) << 7) + ((cb) ^ (((row) & 7) << 4)))

__global__ void __launch_bounds__(256) k_gemm_mma(const float* __restrict__ bias) {
    int nocc = g_boc[0] + g_boc[1] + g_boc[2] + g_boc[3];
    int v0 = blockIdx.y << 7;
    if (v0 >= nocc) return;
    extern __shared__ char smem[];
    uint32_t sbase = smem_u32(smem);
    int tid = threadIdx.x;
    int warp = tid >> 5, lane = tid & 31;
    int c0 = blockIdx.x << 7;
    const float* fb = g_fea + (size_t)v0 * C2;
    const float* wb = g_wr + (size_t)c0 * C2;

    int warp_m0 = (warp >> 2) << 6;
    int warp_n0 = (warp & 3) << 5;

    float acc[4][4][4];
    #pragma unroll
    for (int i = 0; i < 4; i++)
        #pragma unroll
        for (int j = 0; j < 4; j++)
            #pragma unroll
            for (int k = 0; k < 4; k++) acc[i][j][k] = 0.f;

    int lr = tid >> 1;
    int lj0 = (tid & 1) * 4;

    auto load_chunk = [&](int c, int s) {
        int k0 = c * 32;
        uint32_t sA = sbase + s * STAGE_BYTES;
        uint32_t sB = sA + 16384;
        const float* ga = wb + (size_t)lr * C2 + k0 + lj0 * 4;
        const float* gb = fb + (size_t)lr * C2 + k0 + lj0 * 4;
        #pragma unroll
        for (int jj = 0; jj < 4; jj++) {
            uint32_t off = SWZ((uint32_t)lr, (uint32_t)((lj0 + jj) * 16));
            cp_async16(sA + off, ga + jj * 4);
            cp_async16(sB + off, gb + jj * 4);
        }
    };

    #pragma unroll
    for (int s = 0; s < GSTAGES; s++) {
        load_chunk(s, s);
        asm volatile("cp.async.commit_group;" ::: "memory");
    }
    asm volatile("cp.async.wait_group 2;" ::: "memory");
    __syncthreads();

    for (int c = 0; c < NCHUNK; c++) {
        int s = c % GSTAGES;
        uint32_t sA = sbase + s * STAGE_BYTES;
        uint32_t sB = sA + 16384;
        #pragma unroll
        for (int ks = 0; ks < 4; ks++) {
            uint32_t a[4][4];
            #pragma unroll
            for (int mi = 0; mi < 4; mi++) {
                uint32_t row = (uint32_t)(warp_m0 + mi * 16 + (lane & 15));
                uint32_t cb = (uint32_t)(ks * 32 + ((lane >> 4) << 4));
                ldsm_x4(a[mi], sA + SWZ(row, cb));
            }
            uint32_t bf[2][4];
            #pragma unroll
            for (int p = 0; p < 2; p++) {
                uint32_t row = (uint32_t)(warp_n0 + p * 16 + (lane & 7) + ((lane >> 4) << 3));
                uint32_t cb = (uint32_t)(ks * 32 + (((lane >> 3) & 1) << 4));
                ldsm_x4(bf[p], sB + SWZ(row, cb));
            }
            #pragma unroll
            for (int mi = 0; mi < 4; mi++)
                #pragma unroll
                for (int nf = 0; nf < 4; nf++)
                    mma_tf32(acc[mi][nf], a[mi], bf[nf >> 1][(nf & 1) * 2],
                             bf[nf >> 1][(nf & 1) * 2 + 1]);
        }
        __syncthreads();
        if (c + GSTAGES < NCHUNK) load_chunk(c + GSTAGES, s);
        asm volatile("cp.async.commit_group;" ::: "memory");
        asm volatile("cp.async.wait_group 2;" ::: "memory");
        __syncthreads();
    }

    // epilogue: store compact yc = acc + bias; BN partials masked to v < nocc
    #pragma unroll
    for (int mi = 0; mi < 4; mi++) {
        int ch0 = c0 + warp_m0 + mi * 16 + (lane >> 2);
        int ch1 = ch0 + 8;
        float bi0 = (ch0 < C) ? bias[ch0] : 0.f;
        float bi1 = (ch1 < C) ? bias[ch1] : 0.f;
        float* y0 = g_yc + (size_t)(ch0 < C ? ch0 : 0) * NOCCMAX;
        float* y1 = g_yc + (size_t)(ch1 < C ? ch1 : 0) * NOCCMAX;
        float s0 = 0.f, q0 = 0.f, s1 = 0.f, q1 = 0.f;
        #pragma unroll
        for (int nf = 0; nf < 4; nf++) {
            int v = v0 + warp_n0 + nf * 8 + (lane & 3) * 2;
            float a0 = acc[mi][nf][0] + bi0, a1 = acc[mi][nf][1] + bi0;
            float a2 = acc[mi][nf][2] + bi1, a3 = acc[mi][nf][3] + bi1;
            if (ch0 < C) *(float2*)(y0 + v) = make_float2(a0, a1);
            if (ch1 < C) *(float2*)(y1 + v) = make_float2(a2, a3);
            bool m0 = v < nocc, m1 = v + 1 < nocc;
            s0 += (m0 ? a0 : 0.f) + (m1 ? a1 : 0.f);
            q0 += (m0 ? a0 * a0 : 0.f) + (m1 ? a1 * a1 : 0.f);
            s1 += (m0 ? a2 : 0.f) + (m1 ? a3 : 0.f);
            q1 += (m0 ? a2 * a2 : 0.f) + (m1 ? a3 * a3 : 0.f);
        }
        #pragma unroll
        for (int o = 1; o <= 2; o <<= 1) {
            s0 += __shfl_xor_sync(0xffffffffu, s0, o);
            q0 += __shfl_xor_sync(0xffffffffu, q0, o);
            s1 += __shfl_xor_sync(0xffffffffu, s1, o);
            q1 += __shfl_xor_sync(0xffffffffu, q1, o);
        }
        if ((lane & 3) == 0) {
            if (ch0 < C) { atomicAdd(&g_sum[ch0], s0); atomicAdd(&g_sum2[ch0], q0); }
            if (ch1 < C) { atomicAdd(&g_sum[ch1], s1); atomicAdd(&g_sum2[ch1], q1); }
        }
    }
}

// ---------------- K9: expand compact -> dense + BN-finalize + swish ----------------
__global__ void __launch_bounds__(256) k_out(float* __restrict__ y,
                                             const float* __restrict__ bias,
                                             const float* __restrict__ gamma,
                                             const float* __restrict__ beta) {
    size_t i4 = (size_t)blockIdx.x * blockDim.x + threadIdx.x;
    const size_t TOT4 = (size_t)NB * C * R3 / 4;
    if (i4 >= TOT4) return;
    size_t idx = i4 * 4;
    int bc = (int)(idx >> 15);
    int c = bc % C;
    int b = bc / C;
    int v = (int)(idx & (R3 - 1));
    int nocc = g_boc[0] + g_boc[1] + g_boc[2] + g_boc[3];
    int pb = 0;
    #pragma unroll
    for (int j = 0; j < NB; j++) pb += (j < b) ? g_boc[j] : 0;

    float bi = bias[c];
    const float invT = 1.0f / (float)(NB * R3);
    float n_e = (float)(NB * R3 - nocc);
    float mean = (g_sum[c] + n_e * bi) * invT;
    float var = (g_sum2[c] + n_e * bi * bi) * invT - mean * mean;
    float A = gamma[c] * rsqrtf(var + BN_EPS);
    float Bv = beta[c] - mean * A;

    int4 g = *(const int4*)(g_gidx + (b << 15) + v);
    const float* yc = g_yc + (size_t)c * NOCCMAX + pb;
    float x0 = (g.x >= 0) ? yc[g.x] : bi;
    float x1 = (g.y >= 0) ? yc[g.y] : bi;
    float x2 = (g.z >= 0) ? yc[g.z] : bi;
    float x3 = (g.w >= 0) ? yc[g.w] : bi;
    x0 = x0 * A + Bv; x1 = x1 * A + Bv; x2 = x2 * A + Bv; x3 = x3 * A + Bv;
    float4 o;
    o.x = x0 / (1.f + __expf(-x0));
    o.y = x1 / (1.f + __expf(-x1));
    o.z = x2 / (1.f + __expf(-x2));
    o.w = x3 / (1.f + __expf(-x3));
    *(float4*)(y + idx) = o;
}

// ---------------- launch ----------------
extern "C" void kernel_launch(void* const* d_in, const int* in_sizes, int n_in,
                              void* d_out, int out_size) {
    const float* features = (const float*)d_in[0];
    const float* coords   = (const float*)d_in[1];
    const float* w        = (const float*)d_in[2];
    const float* bias     = (const float*)d_in[3];
    const float* gamma    = (const float*)d_in[4];
    const float* beta     = (const float*)d_in[5];
    float* out = (float*)d_out;

    const int Y_SIZE = NB * C * R3;
    const int NC_SIZE = NB * 3 * NP;
    int write_nc = (out_size >= Y_SIZE + NC_SIZE) ? 1 : 0;
    float* nc_out = out + Y_SIZE;

    const int GEMM_SMEM = GSTAGES * STAGE_BYTES;   // 96 KB
    static cudaStream_t s1 = nullptr;
    static cudaEvent_t evA = nullptr, evT = nullptr;
    if (!s1) {
        cudaFuncSetAttribute(k_gemm_mma, cudaFuncAttributeMaxDynamicSharedMemorySize,
                             GEMM_SMEM);
        cudaStreamCreateWithFlags(&s1, cudaStreamNonBlocking);
        cudaEventCreateWithFlags(&evA, cudaEventDisableTiming);
        cudaEventCreateWithFlags(&evT, cudaEventDisableTiming);
    }

    // fork: transpose on s1 overlaps the voxel chain
    cudaEventRecord(evA, 0);
    cudaStreamWaitEvent(s1, evA, 0);
    {
        dim3 blk(32, 8);
        dim3 grd(NP / 32, (C + 31) / 32, NB);
        k_transpose<<<grd, blk, 0, s1>>>(features);
    }
    cudaEventRecord(evT, s1);

    k_setup<<<512, 256>>>(w, coords);
    {
        dim3 grd(NP / 4 / 256, NB);
        k_cmax<<<grd, 256>>>(coords);
    }
    k_voxelize<<<(NB * NP + 255) / 256, 256>>>(coords, nc_out, write_nc);
    k_scan<<<NB, 1024>>>();
    k_scatter<<<(NB * NP + 255) / 256, 256>>>();

    cudaStreamWaitEvent(0, evT, 0);
    k_gather<<<(NVOX) / 8, 256>>>();
    {
        dim3 grd(2, NOCCMAX / 128);   // CTAs beyond nocc early-exit
        k_gemm_mma<<<grd, 256, GEMM_SMEM>>>(bias);
    }
    {
        size_t tot4 = (size_t)NB * C * R3 / 4;
        k_out<<<(unsigned)((tot4 + 255) / 256), 256>>>(out, bias, gamma, beta);
    }
}